// round 5
// baseline (speedup 1.0000x reference)
#include <cuda_runtime.h>

#define NT 8192
#define DD 512
#define EPAD 20
#define SMEM_ATTN (512*16*4 + 512*EPAD*4 + 2*8*512*4 + 128)

__device__ float g_q[NT * DD];
__device__ float g_kT[DD * NT];
__device__ float g_v[NT * DD];
__device__ float g_attn[NT * DD];
__device__ float g_cls[NT];
__device__ float g_Z0;

// ------------------- generic 8192x512 @ 512x512 SGEMM -------------------
// mode 0: C=A@B+bias ; mode 1: store transposed (for kT) ; mode 2: +resid
__global__ __launch_bounds__(256, 2)
void gemm512(const float* __restrict__ A, const float* __restrict__ B,
             const float* __restrict__ bias, const float* __restrict__ resid,
             float* __restrict__ C, int mode)
{
    __shared__ float As[2][8][132];
    __shared__ float Bs[2][8][128];
    const int tid = threadIdx.x;
    const int bm = blockIdx.x * 128, bn = blockIdx.y * 128;
    const int arow = tid >> 1, ak = (tid & 1) << 2;
    const int brow = tid >> 5, bcol = (tid & 31) << 2;
    const int ty = tid >> 4, tx = tid & 15;

    float acc[8][8];
#pragma unroll
    for (int i = 0; i < 8; i++)
#pragma unroll
        for (int j = 0; j < 8; j++) acc[i][j] = 0.f;

    const float* Ap = A + (size_t)(bm + arow) * DD + ak;
    const float* Bp = B + (size_t)brow * DD + bn + bcol;
    float4 av = *(const float4*)Ap;
    float4 bv = *(const float4*)Bp;
    As[0][ak+0][arow]=av.x; As[0][ak+1][arow]=av.y; As[0][ak+2][arow]=av.z; As[0][ak+3][arow]=av.w;
    *(float4*)&Bs[0][brow][bcol] = bv;
    __syncthreads();

    int buf = 0;
#pragma unroll 1
    for (int s = 0; s < 64; s++) {
        if (s < 63) {
            av = *(const float4*)(Ap + (s + 1) * 8);
            bv = *(const float4*)(Bp + (size_t)(s + 1) * 8 * DD);
        }
#pragma unroll
        for (int kt = 0; kt < 8; kt++) {
            float4 a0 = *(float4*)&As[buf][kt][ty*4];
            float4 a1 = *(float4*)&As[buf][kt][64+ty*4];
            float4 b0 = *(float4*)&Bs[buf][kt][tx*4];
            float4 b1 = *(float4*)&Bs[buf][kt][64+tx*4];
            float ar[8]={a0.x,a0.y,a0.z,a0.w,a1.x,a1.y,a1.z,a1.w};
            float br[8]={b0.x,b0.y,b0.z,b0.w,b1.x,b1.y,b1.z,b1.w};
#pragma unroll
            for (int i = 0; i < 8; i++)
#pragma unroll
                for (int j = 0; j < 8; j++) acc[i][j] += ar[i]*br[j];
        }
        if (s < 63) {
            int nb = buf ^ 1;
            As[nb][ak+0][arow]=av.x; As[nb][ak+1][arow]=av.y; As[nb][ak+2][arow]=av.z; As[nb][ak+3][arow]=av.w;
            *(float4*)&Bs[nb][brow][bcol] = bv;
            __syncthreads();
            buf = nb;
        }
    }
#pragma unroll
    for (int ih = 0; ih < 2; ih++)
#pragma unroll
        for (int i = 0; i < 4; i++) {
            int row = bm + ih*64 + ty*4 + i;
#pragma unroll
            for (int jh = 0; jh < 2; jh++) {
                int col = bn + jh*64 + tx*4;
                float4 vv;
                vv.x = acc[ih*4+i][jh*4+0] + bias[col+0];
                vv.y = acc[ih*4+i][jh*4+1] + bias[col+1];
                vv.z = acc[ih*4+i][jh*4+2] + bias[col+2];
                vv.w = acc[ih*4+i][jh*4+3] + bias[col+3];
                if (mode == 2) {
                    float4 r = *(const float4*)&resid[(size_t)row*DD + col];
                    vv.x += r.x; vv.y += r.y; vv.z += r.z; vv.w += r.w;
                }
                if (mode == 1) {
                    C[(size_t)(col+0)*NT + row] = vv.x;
                    C[(size_t)(col+1)*NT + row] = vv.y;
                    C[(size_t)(col+2)*NT + row] = vv.z;
                    C[(size_t)(col+3)*NT + row] = vv.w;
                } else {
                    *(float4*)&C[(size_t)row*DD + col] = vv;
                }
            }
        }
}

// ------------------- fused attention -------------------
__global__ __launch_bounds__(256, 2)
void attn_kernel()
{
    extern __shared__ float sm[];
    float* qT   = sm;                    // [512][16]
    float* e2sT = sm + 512*16;           // [512][EPAD]
    float* kv   = e2sT + 512*EPAD;       // [2][8][512]
    float* red  = kv + 2*8*512;          // [16][2]

    const int tid = threadIdx.x;
    const int w = tid >> 5, lane = tid & 31;
    const int half = (tid >> 5) & 1;
    const int rg = tid >> 6;             // 4 rows each
    const int cg = tid & 63;             // 8 cols each
    const int q0 = blockIdx.x << 4;
    const int lcol = lane << 2;
    const int cc = cg << 3;
    const float scale = 0.044194173824159216f; // 1/sqrt(512)

    { // load q transposed
        const int tr = tid >> 4, tc = (tid & 15) << 2;
#pragma unroll
        for (int it = 0; it < 8; it++) {
            int col = tc + (it << 6);
            float4 qv = *(const float4*)&g_q[(size_t)(q0 + tr)*DD + col];
            qT[(col+0)*16+tr]=qv.x; qT[(col+1)*16+tr]=qv.y;
            qT[(col+2)*16+tr]=qv.z; qT[(col+3)*16+tr]=qv.w;
        }
    }
    float4 O4[4][2];
    float Z[4] = {0.f,0.f,0.f,0.f};
#pragma unroll
    for (int i = 0; i < 4; i++) { O4[i][0]=make_float4(0,0,0,0); O4[i][1]=make_float4(0,0,0,0); }
    __syncthreads();

#pragma unroll 1
    for (int c = 0; c < 16; c++) {
        float4 S4[4][2];
#pragma unroll
        for (int i=0;i<4;i++){S4[i][0]=make_float4(0,0,0,0);S4[i][1]=make_float4(0,0,0,0);}

        // ---- stage A: S = q @ kT_chunk ----
        const float* kb = g_kT + c * 512;
        float4 l0,l1,l2,l3;
        {
            const float* p = kb + (size_t)w*NT + lcol;
            l0=*(const float4*)p; l1=*(const float4*)(p+128);
            l2=*(const float4*)(p+256); l3=*(const float4*)(p+384);
            float* s = kv + w*512 + lcol;
            *(float4*)s=l0; *(float4*)(s+128)=l1; *(float4*)(s+256)=l2; *(float4*)(s+384)=l3;
        }
        __syncthreads();
        int buf = 0;
#pragma unroll 1
        for (int ds = 0; ds < 64; ds++) {
            if (ds < 63) {
                const float* p = kb + (size_t)((ds+1)*8 + w)*NT + lcol;
                l0=*(const float4*)p; l1=*(const float4*)(p+128);
                l2=*(const float4*)(p+256); l3=*(const float4*)(p+384);
            }
#pragma unroll
            for (int kt = 0; kt < 8; kt++) {
                float4 a  = *(float4*)&qT[(ds*8+kt)*16 + (rg<<2)];
                float4 b0 = *(float4*)&kv[buf*4096 + kt*512 + cc];
                float4 b1 = *(float4*)&kv[buf*4096 + kt*512 + cc + 4];
                float ar[4]={a.x,a.y,a.z,a.w};
#pragma unroll
                for (int i=0;i<4;i++){
                    S4[i][0].x+=ar[i]*b0.x; S4[i][0].y+=ar[i]*b0.y;
                    S4[i][0].z+=ar[i]*b0.z; S4[i][0].w+=ar[i]*b0.w;
                    S4[i][1].x+=ar[i]*b1.x; S4[i][1].y+=ar[i]*b1.y;
                    S4[i][1].z+=ar[i]*b1.z; S4[i][1].w+=ar[i]*b1.w;
                }
            }
            if (ds < 63) {
                int nb = buf ^ 1;
                float* s = kv + nb*4096 + w*512 + lcol;
                *(float4*)s=l0; *(float4*)(s+128)=l1; *(float4*)(s+256)=l2; *(float4*)(s+384)=l3;
                __syncthreads();
                buf = nb;
            }
        }

        // ---- chunk softmax + E2 ----
        float p4[4];
#pragma unroll
        for (int i=0;i<4;i++){
            S4[i][0].x=__expf(S4[i][0].x*scale); S4[i][0].y=__expf(S4[i][0].y*scale);
            S4[i][0].z=__expf(S4[i][0].z*scale); S4[i][0].w=__expf(S4[i][0].w*scale);
            S4[i][1].x=__expf(S4[i][1].x*scale); S4[i][1].y=__expf(S4[i][1].y*scale);
            S4[i][1].z=__expf(S4[i][1].z*scale); S4[i][1].w=__expf(S4[i][1].w*scale);
            p4[i]=S4[i][0].x+S4[i][0].y+S4[i][0].z+S4[i][0].w
                 +S4[i][1].x+S4[i][1].y+S4[i][1].z+S4[i][1].w;
        }
#pragma unroll
        for (int off=16; off>0; off>>=1)
#pragma unroll
            for (int i=0;i<4;i++) p4[i]+=__shfl_xor_sync(0xffffffffu,p4[i],off);
        if (lane==0)
#pragma unroll
            for (int i=0;i<4;i++) red[((rg<<2)+i)*2+half]=p4[i];
        __syncthreads();
#pragma unroll
        for (int i=0;i<4;i++){
            float r = 1.f/(red[((rg<<2)+i)*2]+red[((rg<<2)+i)*2+1]);
            S4[i][0].x=__expf(S4[i][0].x*r); S4[i][0].y=__expf(S4[i][0].y*r);
            S4[i][0].z=__expf(S4[i][0].z*r); S4[i][0].w=__expf(S4[i][0].w*r);
            S4[i][1].x=__expf(S4[i][1].x*r); S4[i][1].y=__expf(S4[i][1].y*r);
            S4[i][1].z=__expf(S4[i][1].z*r); S4[i][1].w=__expf(S4[i][1].w*r);
            Z[i]+=S4[i][0].x+S4[i][0].y+S4[i][0].z+S4[i][0].w
                 +S4[i][1].x+S4[i][1].y+S4[i][1].z+S4[i][1].w;
        }
        __syncthreads();   // red reads done before e2sT overwrite region reuse
#pragma unroll
        for (int i=0;i<4;i++){
            int r_ = (rg<<2)+i;
            e2sT[(cc+0)*EPAD+r_]=S4[i][0].x; e2sT[(cc+1)*EPAD+r_]=S4[i][0].y;
            e2sT[(cc+2)*EPAD+r_]=S4[i][0].z; e2sT[(cc+3)*EPAD+r_]=S4[i][0].w;
            e2sT[(cc+4)*EPAD+r_]=S4[i][1].x; e2sT[(cc+5)*EPAD+r_]=S4[i][1].y;
            e2sT[(cc+6)*EPAD+r_]=S4[i][1].z; e2sT[(cc+7)*EPAD+r_]=S4[i][1].w;
        }
        if (blockIdx.x==0 && rg==0) {
            g_cls[c*512+cc+0]=S4[0][0].x; g_cls[c*512+cc+1]=S4[0][0].y;
            g_cls[c*512+cc+2]=S4[0][0].z; g_cls[c*512+cc+3]=S4[0][0].w;
            g_cls[c*512+cc+4]=S4[0][1].x; g_cls[c*512+cc+5]=S4[0][1].y;
            g_cls[c*512+cc+6]=S4[0][1].z; g_cls[c*512+cc+7]=S4[0][1].w;
        }
        __syncthreads();

        // ---- stage B: O += E2 @ V_chunk ----
        const float* vb = g_v + (size_t)(c*512)*DD;
        {
            const float* p = vb + (size_t)w*DD + lcol;
            l0=*(const float4*)p; l1=*(const float4*)(p+128);
            l2=*(const float4*)(p+256); l3=*(const float4*)(p+384);
            float* s = kv + w*512 + lcol;
            *(float4*)s=l0; *(float4*)(s+128)=l1; *(float4*)(s+256)=l2; *(float4*)(s+384)=l3;
        }
        __syncthreads();
        buf = 0;
#pragma unroll 1
        for (int ks = 0; ks < 64; ks++) {
            if (ks < 63) {
                const float* p = vb + (size_t)((ks+1)*8 + w)*DD + lcol;
                l0=*(const float4*)p; l1=*(const float4*)(p+128);
                l2=*(const float4*)(p+256); l3=*(const float4*)(p+384);
            }
#pragma unroll
            for (int kt = 0; kt < 8; kt++) {
                float4 e  = *(float4*)&e2sT[(ks*8+kt)*EPAD + (rg<<2)];
                float4 b0 = *(float4*)&kv[buf*4096 + kt*512 + cc];
                float4 b1 = *(float4*)&kv[buf*4096 + kt*512 + cc + 4];
                float er[4]={e.x,e.y,e.z,e.w};
#pragma unroll
                for (int i=0;i<4;i++){
                    O4[i][0].x+=er[i]*b0.x; O4[i][0].y+=er[i]*b0.y;
                    O4[i][0].z+=er[i]*b0.z; O4[i][0].w+=er[i]*b0.w;
                    O4[i][1].x+=er[i]*b1.x; O4[i][1].y+=er[i]*b1.y;
                    O4[i][1].z+=er[i]*b1.z; O4[i][1].w+=er[i]*b1.w;
                }
            }
            if (ks < 63) {
                int nb = buf ^ 1;
                float* s = kv + nb*4096 + w*512 + lcol;
                *(float4*)s=l0; *(float4*)(s+128)=l1; *(float4*)(s+256)=l2; *(float4*)(s+384)=l3;
                __syncthreads();
                buf = nb;
            }
        }
        __syncthreads();
    }

    // ---- final Z reduce + store ----
#pragma unroll
    for (int off=16; off>0; off>>=1)
#pragma unroll
        for (int i=0;i<4;i++) Z[i]+=__shfl_xor_sync(0xffffffffu,Z[i],off);
    if (lane==0)
#pragma unroll
        for (int i=0;i<4;i++) red[((rg<<2)+i)*2+half]=Z[i];
    __syncthreads();
#pragma unroll
    for (int i=0;i<4;i++){
        float zi = red[((rg<<2)+i)*2]+red[((rg<<2)+i)*2+1];
        float r = 1.f/zi;
        int row = q0 + (rg<<2) + i;
        float4 o0=O4[i][0], o1=O4[i][1];
        o0.x*=r;o0.y*=r;o0.z*=r;o0.w*=r; o1.x*=r;o1.y*=r;o1.z*=r;o1.w*=r;
        *(float4*)&g_attn[(size_t)row*DD + cc]     = o0;
        *(float4*)&g_attn[(size_t)row*DD + cc + 4] = o1;
        if (row==0 && cg==0) g_Z0 = zi;
    }
}

__global__ void cls_kernel(float* __restrict__ out)
{
    int m = blockIdx.x * 256 + threadIdx.x;
    out[m] = g_cls[m] / g_Z0;
}

extern "C" void kernel_launch(void* const* d_in, const int* in_sizes, int n_in,
                              void* d_out, int out_size)
{
    const float* x  = (const float*)d_in[0];
    const float* Wq = (const float*)d_in[1];
    const float* bq = (const float*)d_in[2];
    const float* Wk = (const float*)d_in[3];
    const float* bk = (const float*)d_in[4];
    const float* Wv = (const float*)d_in[5];
    const float* bv = (const float*)d_in[6];
    const float* Wo = (const float*)d_in[7];
    const float* bo = (const float*)d_in[8];
    float* out = (float*)d_out;

    float *q, *kT, *v, *attn;
    cudaGetSymbolAddress((void**)&q, g_q);
    cudaGetSymbolAddress((void**)&kT, g_kT);
    cudaGetSymbolAddress((void**)&v, g_v);
    cudaGetSymbolAddress((void**)&attn, g_attn);

    cudaFuncSetAttribute(attn_kernel, cudaFuncAttributeMaxDynamicSharedMemorySize, SMEM_ATTN);

    dim3 gg(64, 4);
    gemm512<<<gg, 256>>>(x, Wq, bq, nullptr, q, 0);
    gemm512<<<gg, 256>>>(x, Wk, bk, nullptr, kT, 1);
    gemm512<<<gg, 256>>>(x, Wv, bv, nullptr, v, 0);
    attn_kernel<<<512, 256, SMEM_ATTN>>>();
    gemm512<<<gg, 256>>>(attn, Wo, bo, x, out, 2);
    cls_kernel<<<32, 256>>>(out + (size_t)NT * DD);
}

// round 8
// speedup vs baseline: 5.5471x; 5.5471x over previous
#include <cuda_runtime.h>
#include <cuda_bf16.h>
#include <cstdint>

constexpr int NTOK = 8192;
constexpr int DMOD = 512;

__device__ __nv_bfloat16 g_qb[NTOK * DMOD];
__device__ __nv_bfloat16 g_kb[NTOK * DMOD];
__device__ __nv_bfloat16 g_vb[NTOK * DMOD];
__device__ float g_attn[NTOK * DMOD];
__device__ float g_cls[NTOK];
__device__ float g_Z0;

// smem byte map: Q[0,32K) E[32K,64K) KVstage[64K,192K) srow[192K,+512) Zb[+512,+128)
constexpr int EOFF = 32768;
constexpr int SOFF = 65536;
constexpr int ROFF = 196608;
constexpr int ZOFF = 197120;
constexpr int SM_TOTAL = 197376;

__device__ __forceinline__ void ldm4(uint32_t &r0, uint32_t &r1, uint32_t &r2, uint32_t &r3, uint32_t ad)
{
    asm volatile("ldmatrix.sync.aligned.m8n8.x4.shared.b16 {%0,%1,%2,%3},[%4];"
                 : "=r"(r0), "=r"(r1), "=r"(r2), "=r"(r3) : "r"(ad));
}

__device__ __forceinline__ void ldm4t(uint32_t &r0, uint32_t &r1, uint32_t &r2, uint32_t &r3, uint32_t ad)
{
    asm volatile("ldmatrix.sync.aligned.m8n8.x4.trans.shared.b16 {%0,%1,%2,%3},[%4];"
                 : "=r"(r0), "=r"(r1), "=r"(r2), "=r"(r3) : "r"(ad));
}

__device__ __forceinline__ void mmab(float &c0, float &c1, float &c2, float &c3,
                                     uint32_t a0, uint32_t a1, uint32_t a2, uint32_t a3,
                                     uint32_t b0, uint32_t b1)
{
    asm volatile("mma.sync.aligned.m16n8k16.row.col.f32.bf16.bf16.f32 "
                 "{%0,%1,%2,%3},{%4,%5,%6,%7},{%8,%9},{%0,%1,%2,%3};"
                 : "+f"(c0), "+f"(c1), "+f"(c2), "+f"(c3)
                 : "r"(a0), "r"(a1), "r"(a2), "r"(a3), "r"(b0), "r"(b1));
}

__device__ __forceinline__ void cpa16(uint32_t s, const void* g)
{
    asm volatile("cp.async.cg.shared.global [%0],[%1],16;" :: "r"(s), "l"(g));
}

__device__ __forceinline__ void cpcommit() { asm volatile("cp.async.commit_group;"); }
__device__ __forceinline__ void cpwait0()  { asm volatile("cp.async.wait_group 0;"); }

// stage one 64-row x 512-col bf16 tile (64KB) into smem, swizzled
__device__ __forceinline__ void stage64(uint32_t sbase, const __nv_bfloat16* g, int tid)
{
#pragma unroll
    for (int i = 0; i < 16; i++) {
        int idx = i * 256 + tid;
        int row = idx >> 6;
        int c16 = idx & 63;
        cpa16(sbase + (uint32_t)(row * 1024 + ((c16 ^ (row & 7)) << 4)),
              (const char*)g + (size_t)row * 1024 + (size_t)c16 * 16);
    }
}

__global__ __launch_bounds__(256)
void attn2()
{
    extern __shared__ char sm[];
    uint32_t sb = (uint32_t)__cvta_generic_to_shared(sm);
    float* srow = (float*)(sm + ROFF);
    float* Zb   = (float*)(sm + ZOFF);

    const int tid  = threadIdx.x;
    const int wd   = tid >> 5;
    const int lane = tid & 31;
    const int r8   = lane & 7;
    const int jj   = lane >> 3;
    const int gid  = lane >> 2;
    const int tig  = lane & 3;
    const int wm   = wd >> 2;
    const int wn   = wd & 3;
    const int q0   = blockIdx.x << 5;
    const float SC = 0.044194173824159216f;  // 1/sqrt(512)

    if (tid < 32)  Zb[tid] = 0.f;
    if (tid < 128) srow[tid] = 0.f;

    // Q tile (32x512 bf16) -> smem swizzled
    const char* qg = (const char*)(g_qb + (size_t)q0 * DMOD);
#pragma unroll
    for (int i = 0; i < 8; i++) {
        int idx = i * 256 + tid;
        int row = idx >> 6;
        int c16 = idx & 63;
        *(uint4*)(sm + row * 1024 + ((c16 ^ (row & 7)) << 4)) =
            *(const uint4*)(qg + (size_t)row * 1024 + (size_t)c16 * 16);
    }

    const int rA  = wm * 16 + r8 + ((jj & 1) << 3);
    const int cA8 = jj >> 1;
    const int rB  = wn * 16 + r8 + ((jj >> 1) << 3);
    const int cB8 = jj & 1;
    const int rP  = r8 + ((jj & 1) << 3);
    const int cP8 = jj >> 1;

    float O[2][8][4];
#pragma unroll
    for (int x1 = 0; x1 < 2; x1++) {
#pragma unroll
        for (int x2 = 0; x2 < 8; x2++) {
#pragma unroll
            for (int x3 = 0; x3 < 4; x3++) { O[x1][x2][x3] = 0.f; }
        }
    }

    int pb = 0;
    stage64(sb + SOFF, g_kb, tid);
    cpcommit();

    for (int c = 0; c < 16; c++) {
        // ---------- QK pass: E1 for a 512-key chunk ----------
        for (int kb = 0; kb < 8; kb++) {
            cpwait0();
            __syncthreads();
            const __nv_bfloat16* nx;
            if (kb < 7) { nx = g_kb + ((size_t)c * 512 + (size_t)(kb + 1) * 64) * DMOD; }
            else        { nx = g_vb + ((size_t)c * 512) * DMOD; }
            stage64(sb + SOFF + ((uint32_t)(pb ^ 1) << 16), nx, tid);
            cpcommit();
            uint32_t stg = sb + SOFF + ((uint32_t)pb << 16);

            float S00 = 0.f, S01 = 0.f, S02 = 0.f, S03 = 0.f;
            float S10 = 0.f, S11 = 0.f, S12 = 0.f, S13 = 0.f;
#pragma unroll 4
            for (int ks = 0; ks < 32; ks++) {
                uint32_t a0, a1, a2, a3, b0, b1, b2, b3;
                int ca = 2 * ks + cA8;
                ldm4(a0, a1, a2, a3, sb + (uint32_t)(rA * 1024 + ((ca ^ (rA & 7)) << 4)));
                int cb = 2 * ks + cB8;
                ldm4(b0, b1, b2, b3, stg + (uint32_t)(rB * 1024 + ((cb ^ (rB & 7)) << 4)));
                mmab(S00, S01, S02, S03, a0, a1, a2, a3, b0, b1);
                mmab(S10, S11, S12, S13, a0, a1, a2, a3, b2, b3);
            }
            // exp(S*SC) -> E1 (bf16, smem), partial row sums
            float e0 = __expf(S00 * SC), e1 = __expf(S01 * SC);
            float e2 = __expf(S02 * SC), e3 = __expf(S03 * SC);
            float f0 = __expf(S10 * SC), f1 = __expf(S11 * SC);
            float f2 = __expf(S12 * SC), f3 = __expf(S13 * SC);
            float p0 = e0 + e1 + f0 + f1;
            float p1 = e2 + e3 + f2 + f3;
            int rw0 = wm * 16 + gid;
            int rw1 = rw0 + 8;
            int col0 = kb * 64 + wn * 16 + tig * 2;
            int col1 = col0 + 8;
            *(__nv_bfloat162*)(sm + EOFF + rw0 * 1024 + (((col0 >> 3) ^ (rw0 & 7)) << 4) + ((col0 & 7) << 1)) = __floats2bfloat162_rn(e0, e1);
            *(__nv_bfloat162*)(sm + EOFF + rw1 * 1024 + (((col0 >> 3) ^ (rw1 & 7)) << 4) + ((col0 & 7) << 1)) = __floats2bfloat162_rn(e2, e3);
            *(__nv_bfloat162*)(sm + EOFF + rw0 * 1024 + (((col1 >> 3) ^ (rw0 & 7)) << 4) + ((col1 & 7) << 1)) = __floats2bfloat162_rn(f0, f1);
            *(__nv_bfloat162*)(sm + EOFF + rw1 * 1024 + (((col1 >> 3) ^ (rw1 & 7)) << 4) + ((col1 & 7) << 1)) = __floats2bfloat162_rn(f2, f3);
            p0 += __shfl_xor_sync(0xffffffffu, p0, 1);
            p0 += __shfl_xor_sync(0xffffffffu, p0, 2);
            p1 += __shfl_xor_sync(0xffffffffu, p1, 1);
            p1 += __shfl_xor_sync(0xffffffffu, p1, 2);
            if (tig == 0) {
                srow[wn * 32 + wm * 16 + gid]     += p0;
                srow[wn * 32 + wm * 16 + gid + 8] += p1;
            }
            pb ^= 1;
        }
        __syncthreads();

        // ---------- chunk softmax -> E2 in place, Z accum, cls ----------
        {
            int row = tid >> 3;
            int seg = tid & 7;
            float rinv = 1.f / (srow[row] + srow[32 + row] + srow[64 + row] + srow[96 + row]);
            float z = 0.f;
#pragma unroll
            for (int i = 0; i < 8; i++) {
                int c16 = seg * 8 + i;
                uint32_t* p = (uint32_t*)(sm + EOFF + row * 1024 + ((c16 ^ (row & 7)) << 4));
#pragma unroll
                for (int qq = 0; qq < 4; qq++) {
                    float2 fv = __bfloat1622float2(*(__nv_bfloat162*)(p + qq));
                    float u0 = __expf(fv.x * rinv);
                    float u1 = __expf(fv.y * rinv);
                    z += u0 + u1;
                    *(__nv_bfloat162*)(p + qq) = __floats2bfloat162_rn(u0, u1);
                    if (blockIdx.x == 0 && row == 0) {
                        int col = c16 * 8 + qq * 2;
                        g_cls[c * 512 + col]     = u0;
                        g_cls[c * 512 + col + 1] = u1;
                    }
                }
            }
            z += __shfl_xor_sync(0xffffffffu, z, 1);
            z += __shfl_xor_sync(0xffffffffu, z, 2);
            z += __shfl_xor_sync(0xffffffffu, z, 4);
            if (seg == 0) Zb[row] += z;
        }

        // ---------- PV pass: O += E2 @ V_chunk ----------
        for (int kb = 0; kb < 8; kb++) {
            cpwait0();
            __syncthreads();
            if (kb == 0 && tid < 128) srow[tid] = 0.f;
            if (kb < 7) {
                stage64(sb + SOFF + ((uint32_t)(pb ^ 1) << 16),
                        g_vb + ((size_t)c * 512 + (size_t)(kb + 1) * 64) * DMOD, tid);
                cpcommit();
            } else if (c < 15) {
                stage64(sb + SOFF + ((uint32_t)(pb ^ 1) << 16),
                        g_kb + ((size_t)(c + 1) * 512) * DMOD, tid);
                cpcommit();
            }
            uint32_t stg = sb + SOFF + ((uint32_t)pb << 16);
#pragma unroll
            for (int ks = 0; ks < 4; ks++) {
                uint32_t a00, a01, a02, a03, a10, a11, a12, a13;
                int ce  = kb * 8 + ks * 2 + cP8;
                int ra1 = 16 + rP;
                ldm4(a00, a01, a02, a03, sb + (uint32_t)(EOFF + rP  * 1024 + ((ce ^ (rP  & 7)) << 4)));
                ldm4(a10, a11, a12, a13, sb + (uint32_t)(EOFF + ra1 * 1024 + ((ce ^ (ra1 & 7)) << 4)));
                int rv = ks * 16 + rP;
#pragma unroll
                for (int nt = 0; nt < 4; nt++) {
                    uint32_t b0, b1, b2, b3;
                    int cv = wd * 8 + nt * 2 + cP8;
                    ldm4t(b0, b1, b2, b3, stg + (uint32_t)(rv * 1024 + ((cv ^ (rv & 7)) << 4)));
                    mmab(O[0][2*nt  ][0], O[0][2*nt  ][1], O[0][2*nt  ][2], O[0][2*nt  ][3], a00, a01, a02, a03, b0, b1);
                    mmab(O[0][2*nt+1][0], O[0][2*nt+1][1], O[0][2*nt+1][2], O[0][2*nt+1][3], a00, a01, a02, a03, b2, b3);
                    mmab(O[1][2*nt  ][0], O[1][2*nt  ][1], O[1][2*nt  ][2], O[1][2*nt  ][3], a10, a11, a12, a13, b0, b1);
                    mmab(O[1][2*nt+1][0], O[1][2*nt+1][1], O[1][2*nt+1][2], O[1][2*nt+1][3], a10, a11, a12, a13, b2, b3);
                }
            }
            pb ^= 1;
        }
    }
    __syncthreads();

    // ---------- normalize + store ----------
#pragma unroll
    for (int mt = 0; mt < 2; mt++) {
        int r0 = mt * 16 + gid;
        float z0 = 1.f / Zb[r0];
        float z1 = 1.f / Zb[r0 + 8];
#pragma unroll
        for (int nt = 0; nt < 8; nt++) {
            int col = wd * 64 + nt * 8 + tig * 2;
            float2 v0 = make_float2(O[mt][nt][0] * z0, O[mt][nt][1] * z0);
            float2 v1 = make_float2(O[mt][nt][2] * z1, O[mt][nt][3] * z1);
            *(float2*)&g_attn[(size_t)(q0 + r0) * DMOD + col]     = v0;
            *(float2*)&g_attn[(size_t)(q0 + r0 + 8) * DMOD + col] = v1;
        }
    }
    if (blockIdx.x == 0 && tid == 0) g_Z0 = Zb[0];
}

// projection GEMM: mode 3 = bf16 out (+bias), mode 2 = fp32 +bias+residual
__global__ __launch_bounds__(256, 2)
void gemm512(const float* __restrict__ A, const float* __restrict__ B,
             const float* __restrict__ bias, const float* __restrict__ resid,
             float* __restrict__ C, __nv_bfloat16* __restrict__ Cb, int mode)
{
    __shared__ float As[2][8][132];
    __shared__ float Bs[2][8][128];
    const int tid  = threadIdx.x;
    const int bm   = blockIdx.x * 128;
    const int bn   = blockIdx.y * 128;
    const int arow = tid >> 1;
    const int ak   = (tid & 1) << 2;
    const int brow = tid >> 5;
    const int bcol = (tid & 31) << 2;
    const int ty   = tid >> 4;
    const int tx   = tid & 15;

    float acc[8][8];
#pragma unroll
    for (int i = 0; i < 8; i++) {
#pragma unroll
        for (int j2 = 0; j2 < 8; j2++) { acc[i][j2] = 0.f; }
    }

    const float* Ap = A + (size_t)(bm + arow) * DMOD + ak;
    const float* Bp = B + (size_t)brow * DMOD + bn + bcol;
    float4 av = *(const float4*)Ap;
    float4 bv = *(const float4*)Bp;
    As[0][ak + 0][arow] = av.x; As[0][ak + 1][arow] = av.y;
    As[0][ak + 2][arow] = av.z; As[0][ak + 3][arow] = av.w;
    *(float4*)&Bs[0][brow][bcol] = bv;
    __syncthreads();

    int buf = 0;
#pragma unroll 1
    for (int s = 0; s < 64; s++) {
        if (s < 63) {
            av = *(const float4*)(Ap + (s + 1) * 8);
            bv = *(const float4*)(Bp + (size_t)(s + 1) * 8 * DMOD);
        }
#pragma unroll
        for (int kt = 0; kt < 8; kt++) {
            float4 a0 = *(float4*)&As[buf][kt][ty * 4];
            float4 a1 = *(float4*)&As[buf][kt][64 + ty * 4];
            float4 b0 = *(float4*)&Bs[buf][kt][tx * 4];
            float4 b1 = *(float4*)&Bs[buf][kt][64 + tx * 4];
            float ar[8] = {a0.x, a0.y, a0.z, a0.w, a1.x, a1.y, a1.z, a1.w};
            float br[8] = {b0.x, b0.y, b0.z, b0.w, b1.x, b1.y, b1.z, b1.w};
#pragma unroll
            for (int i = 0; i < 8; i++) {
#pragma unroll
                for (int j2 = 0; j2 < 8; j2++) { acc[i][j2] += ar[i] * br[j2]; }
            }
        }
        if (s < 63) {
            int nb = buf ^ 1;
            As[nb][ak + 0][arow] = av.x; As[nb][ak + 1][arow] = av.y;
            As[nb][ak + 2][arow] = av.z; As[nb][ak + 3][arow] = av.w;
            *(float4*)&Bs[nb][brow][bcol] = bv;
            __syncthreads();
            buf = nb;
        }
    }

#pragma unroll
    for (int ih = 0; ih < 2; ih++) {
#pragma unroll
        for (int i = 0; i < 4; i++) {
            int row = bm + ih * 64 + ty * 4 + i;
#pragma unroll
            for (int jh = 0; jh < 2; jh++) {
                int col = bn + jh * 64 + tx * 4;
                float4 vv;
                vv.x = acc[ih * 4 + i][jh * 4 + 0] + bias[col + 0];
                vv.y = acc[ih * 4 + i][jh * 4 + 1] + bias[col + 1];
                vv.z = acc[ih * 4 + i][jh * 4 + 2] + bias[col + 2];
                vv.w = acc[ih * 4 + i][jh * 4 + 3] + bias[col + 3];
                if (mode == 3) {
                    *(__nv_bfloat162*)&Cb[(size_t)row * DMOD + col]     = __floats2bfloat162_rn(vv.x, vv.y);
                    *(__nv_bfloat162*)&Cb[(size_t)row * DMOD + col + 2] = __floats2bfloat162_rn(vv.z, vv.w);
                } else {
                    float4 rr = *(const float4*)&resid[(size_t)row * DMOD + col];
                    vv.x += rr.x; vv.y += rr.y; vv.z += rr.z; vv.w += rr.w;
                    *(float4*)&C[(size_t)row * DMOD + col] = vv;
                }
            }
        }
    }
}

__global__ void cls_kernel(float* __restrict__ out)
{
    int m = blockIdx.x * 256 + threadIdx.x;
    out[m] = g_cls[m] / g_Z0;
}

extern "C" void kernel_launch(void* const* d_in, const int* in_sizes, int n_in,
                              void* d_out, int out_size)
{
    const float* x  = (const float*)d_in[0];
    const float* Wq = (const float*)d_in[1];
    const float* bq = (const float*)d_in[2];
    const float* Wk = (const float*)d_in[3];
    const float* bk = (const float*)d_in[4];
    const float* Wv = (const float*)d_in[5];
    const float* bv = (const float*)d_in[6];
    const float* Wo = (const float*)d_in[7];
    const float* bo = (const float*)d_in[8];
    float* out = (float*)d_out;

    __nv_bfloat16* qb = 0;
    __nv_bfloat16* kb = 0;
    __nv_bfloat16* vb = 0;
    float* attn = 0;
    cudaGetSymbolAddress((void**)&qb, g_qb);
    cudaGetSymbolAddress((void**)&kb, g_kb);
    cudaGetSymbolAddress((void**)&vb, g_vb);
    cudaGetSymbolAddress((void**)&attn, g_attn);

    cudaFuncSetAttribute(attn2, cudaFuncAttributeMaxDynamicSharedMemorySize, SM_TOTAL);

    dim3 gg(64, 4);
    gemm512<<<gg, 256>>>(x, Wq, bq, (const float*)0, (float*)0, qb, 3);
    gemm512<<<gg, 256>>>(x, Wk, bk, (const float*)0, (float*)0, kb, 3);
    gemm512<<<gg, 256>>>(x, Wv, bv, (const float*)0, (float*)0, vb, 3);
    attn2<<<256, 256, SM_TOTAL>>>();
    gemm512<<<gg, 256>>>(attn, Wo, bo, x, out, (__nv_bfloat16*)0, 2);
    cls_kernel<<<32, 256>>>(out + (size_t)NTOK * DMOD);
}

// round 9
// speedup vs baseline: 5.7917x; 1.0441x over previous
#include <cuda_runtime.h>
#include <cuda_bf16.h>
#include <cstdint>

constexpr int NTOK = 8192;
constexpr int DMOD = 512;

__device__ __nv_bfloat16 g_xb[NTOK * DMOD];
__device__ __nv_bfloat16 g_w0[DMOD * DMOD];
__device__ __nv_bfloat16 g_w1[DMOD * DMOD];
__device__ __nv_bfloat16 g_w2[DMOD * DMOD];
__device__ __nv_bfloat16 g_qb[NTOK * DMOD];
__device__ __nv_bfloat16 g_kb[NTOK * DMOD];
__device__ __nv_bfloat16 g_vb[NTOK * DMOD];
__device__ float g_attn[NTOK * DMOD];
__device__ float g_cls[NTOK];
__device__ float g_Z0;

// attn2 smem map: Q[0,32K) E[32K,64K) KVstage[64K,192K) srow[192K,+1K) Zb[+128]
constexpr int EOFF = 32768;
constexpr int SOFF = 65536;
constexpr int ROFF = 196608;
constexpr int ZOFF = 197632;
constexpr int SM_TOTAL = 197760;

__device__ __forceinline__ void ldm4(uint32_t &r0, uint32_t &r1, uint32_t &r2, uint32_t &r3, uint32_t ad)
{
    asm volatile("ldmatrix.sync.aligned.m8n8.x4.shared.b16 {%0,%1,%2,%3},[%4];"
                 : "=r"(r0), "=r"(r1), "=r"(r2), "=r"(r3) : "r"(ad));
}
__device__ __forceinline__ void ldm2(uint32_t &r0, uint32_t &r1, uint32_t ad)
{
    asm volatile("ldmatrix.sync.aligned.m8n8.x2.shared.b16 {%0,%1},[%2];"
                 : "=r"(r0), "=r"(r1) : "r"(ad));
}
__device__ __forceinline__ void ldm4t(uint32_t &r0, uint32_t &r1, uint32_t &r2, uint32_t &r3, uint32_t ad)
{
    asm volatile("ldmatrix.sync.aligned.m8n8.x4.trans.shared.b16 {%0,%1,%2,%3},[%4];"
                 : "=r"(r0), "=r"(r1), "=r"(r2), "=r"(r3) : "r"(ad));
}
__device__ __forceinline__ void mmab(float &c0, float &c1, float &c2, float &c3,
                                     uint32_t a0, uint32_t a1, uint32_t a2, uint32_t a3,
                                     uint32_t b0, uint32_t b1)
{
    asm volatile("mma.sync.aligned.m16n8k16.row.col.f32.bf16.bf16.f32 "
                 "{%0,%1,%2,%3},{%4,%5,%6,%7},{%8,%9},{%0,%1,%2,%3};"
                 : "+f"(c0), "+f"(c1), "+f"(c2), "+f"(c3)
                 : "r"(a0), "r"(a1), "r"(a2), "r"(a3), "r"(b0), "r"(b1));
}
__device__ __forceinline__ void cpa16(uint32_t s, const void* g)
{
    asm volatile("cp.async.cg.shared.global [%0],[%1],16;" :: "r"(s), "l"(g));
}
__device__ __forceinline__ void cpcommit() { asm volatile("cp.async.commit_group;"); }
__device__ __forceinline__ void cpwait0()  { asm volatile("cp.async.wait_group 0;"); }

// stage one 64-row x 512-col bf16 tile (64KB) into smem, swizzled; 512 threads
__device__ __forceinline__ void stage64(uint32_t sbase, const __nv_bfloat16* g, int tid)
{
#pragma unroll
    for (int i = 0; i < 8; i++) {
        int idx = i * 512 + tid;
        int row = idx >> 6;
        int c16 = idx & 63;
        cpa16(sbase + (uint32_t)(row * 1024 + ((c16 ^ (row & 7)) << 4)),
              (const char*)g + (size_t)row * 1024 + (size_t)c16 * 16);
    }
}

__global__ __launch_bounds__(512)
void attn2()
{
    extern __shared__ char sm[];
    uint32_t sb = (uint32_t)__cvta_generic_to_shared(sm);
    float* srow = (float*)(sm + ROFF);
    float* Zb   = (float*)(sm + ZOFF);

    const int tid  = threadIdx.x;
    const int wd   = tid >> 5;
    const int lane = tid & 31;
    const int r8   = lane & 7;
    const int jj   = lane >> 3;
    const int gid  = lane >> 2;
    const int tig  = lane & 3;
    const int wm   = wd >> 3;   // 0..1
    const int wn   = wd & 7;    // 0..7
    const int q0   = blockIdx.x << 5;
    const float SC = 0.044194173824159216f;  // 1/sqrt(512)

    if (tid < 32)  Zb[tid] = 0.f;
    if (tid < 256) srow[tid] = 0.f;

    // Q tile (32x512 bf16) -> smem swizzled
    const char* qg = (const char*)(g_qb + (size_t)q0 * DMOD);
#pragma unroll
    for (int i = 0; i < 4; i++) {
        int idx = i * 512 + tid;
        int row = idx >> 6;
        int c16 = idx & 63;
        *(uint4*)(sm + row * 1024 + ((c16 ^ (row & 7)) << 4)) =
            *(const uint4*)(qg + (size_t)row * 1024 + (size_t)c16 * 16);
    }

    const int rA  = wm * 16 + r8 + ((jj & 1) << 3);
    const int cA8 = jj >> 1;
    const int rBq = wn * 8 + r8;     // x2 B load row (lanes 0..15 matter)
    const int cB8 = jj & 1;
    const int rP  = r8 + ((jj & 1) << 3);
    const int cP8 = jj >> 1;

    float O[8][4];
#pragma unroll
    for (int x2 = 0; x2 < 8; x2++) {
#pragma unroll
        for (int x3 = 0; x3 < 4; x3++) { O[x2][x3] = 0.f; }
    }

    int pb = 0;
    stage64(sb + SOFF, g_kb, tid);
    cpcommit();

    for (int c = 0; c < 16; c++) {
        // ---------- QK pass: E1 for a 512-key chunk ----------
        for (int kb = 0; kb < 8; kb++) {
            cpwait0();
            __syncthreads();
            const __nv_bfloat16* nx;
            if (kb < 7) { nx = g_kb + ((size_t)c * 512 + (size_t)(kb + 1) * 64) * DMOD; }
            else        { nx = g_vb + ((size_t)c * 512) * DMOD; }
            stage64(sb + SOFF + ((uint32_t)(pb ^ 1) << 16), nx, tid);
            cpcommit();
            uint32_t stg = sb + SOFF + ((uint32_t)pb << 16);

            float S0 = 0.f, S1 = 0.f, S2 = 0.f, S3 = 0.f;
#pragma unroll 4
            for (int ks = 0; ks < 32; ks++) {
                uint32_t a0, a1, a2, a3, b0, b1;
                int ca = 2 * ks + cA8;
                ldm4(a0, a1, a2, a3, sb + (uint32_t)(rA * 1024 + ((ca ^ (rA & 7)) << 4)));
                int cb = 2 * ks + cB8;
                ldm2(b0, b1, stg + (uint32_t)(rBq * 1024 + ((cb ^ (rBq & 7)) << 4)));
                mmab(S0, S1, S2, S3, a0, a1, a2, a3, b0, b1);
            }
            float e0 = __expf(S0 * SC), e1 = __expf(S1 * SC);
            float e2 = __expf(S2 * SC), e3 = __expf(S3 * SC);
            float p0 = e0 + e1;
            float p1 = e2 + e3;
            int rw0 = wm * 16 + gid;
            int rw1 = rw0 + 8;
            int col0 = kb * 64 + wn * 8 + tig * 2;
            *(__nv_bfloat162*)(sm + EOFF + rw0 * 1024 + (((col0 >> 3) ^ (rw0 & 7)) << 4) + ((col0 & 7) << 1)) = __floats2bfloat162_rn(e0, e1);
            *(__nv_bfloat162*)(sm + EOFF + rw1 * 1024 + (((col0 >> 3) ^ (rw1 & 7)) << 4) + ((col0 & 7) << 1)) = __floats2bfloat162_rn(e2, e3);
            p0 += __shfl_xor_sync(0xffffffffu, p0, 1);
            p0 += __shfl_xor_sync(0xffffffffu, p0, 2);
            p1 += __shfl_xor_sync(0xffffffffu, p1, 1);
            p1 += __shfl_xor_sync(0xffffffffu, p1, 2);
            if (tig == 0) {
                srow[wn * 32 + wm * 16 + gid]     += p0;
                srow[wn * 32 + wm * 16 + gid + 8] += p1;
            }
            pb ^= 1;
        }
        __syncthreads();

        // ---------- chunk softmax -> E2 in place, Z accum, cls ----------
        {
            int row = tid >> 4;
            int seg = tid & 15;
            float s = 0.f;
#pragma unroll
            for (int g = 0; g < 8; g++) { s += srow[g * 32 + row]; }
            float rinv = 1.f / s;
            float z = 0.f;
#pragma unroll
            for (int i = 0; i < 4; i++) {
                int c16 = seg * 4 + i;
                uint32_t* p = (uint32_t*)(sm + EOFF + row * 1024 + ((c16 ^ (row & 7)) << 4));
#pragma unroll
                for (int qq = 0; qq < 4; qq++) {
                    float2 fv = __bfloat1622float2(*(__nv_bfloat162*)(p + qq));
                    float u0 = __expf(fv.x * rinv);
                    float u1 = __expf(fv.y * rinv);
                    z += u0 + u1;
                    *(__nv_bfloat162*)(p + qq) = __floats2bfloat162_rn(u0, u1);
                    if (blockIdx.x == 0 && row == 0) {
                        int col = c16 * 8 + qq * 2;
                        g_cls[c * 512 + col]     = u0;
                        g_cls[c * 512 + col + 1] = u1;
                    }
                }
            }
            z += __shfl_xor_sync(0xffffffffu, z, 1);
            z += __shfl_xor_sync(0xffffffffu, z, 2);
            z += __shfl_xor_sync(0xffffffffu, z, 4);
            z += __shfl_xor_sync(0xffffffffu, z, 8);
            if (seg == 0) Zb[row] += z;
        }

        // ---------- PV pass: O += E2 @ V_chunk ----------
        for (int kb = 0; kb < 8; kb++) {
            cpwait0();
            __syncthreads();
            if (kb == 0 && tid < 256) srow[tid] = 0.f;
            if (kb < 7) {
                stage64(sb + SOFF + ((uint32_t)(pb ^ 1) << 16),
                        g_vb + ((size_t)c * 512 + (size_t)(kb + 1) * 64) * DMOD, tid);
                cpcommit();
            } else if (c < 15) {
                stage64(sb + SOFF + ((uint32_t)(pb ^ 1) << 16),
                        g_kb + ((size_t)(c + 1) * 512) * DMOD, tid);
                cpcommit();
            }
            uint32_t stg = sb + SOFF + ((uint32_t)pb << 16);
            int rowA = wm * 16 + rP;
#pragma unroll
            for (int ks = 0; ks < 4; ks++) {
                uint32_t a0, a1, a2, a3;
                int ce = kb * 8 + ks * 2 + cP8;
                ldm4(a0, a1, a2, a3, sb + (uint32_t)(EOFF + rowA * 1024 + ((ce ^ (rowA & 7)) << 4)));
                int rv = ks * 16 + rP;
#pragma unroll
                for (int nt2 = 0; nt2 < 4; nt2++) {
                    uint32_t b0, b1, b2, b3;
                    int cv = wn * 8 + nt2 * 2 + cP8;
                    ldm4t(b0, b1, b2, b3, stg + (uint32_t)(rv * 1024 + ((cv ^ (rv & 7)) << 4)));
                    mmab(O[2*nt2  ][0], O[2*nt2  ][1], O[2*nt2  ][2], O[2*nt2  ][3], a0, a1, a2, a3, b0, b1);
                    mmab(O[2*nt2+1][0], O[2*nt2+1][1], O[2*nt2+1][2], O[2*nt2+1][3], a0, a1, a2, a3, b2, b3);
                }
            }
            pb ^= 1;
        }
    }
    __syncthreads();

    // ---------- normalize + store ----------
    {
        int r0 = wm * 16 + gid;
        float z0 = 1.f / Zb[r0];
        float z1 = 1.f / Zb[r0 + 8];
#pragma unroll
        for (int nt = 0; nt < 8; nt++) {
            int col = wn * 64 + nt * 8 + tig * 2;
            float2 v0 = make_float2(O[nt][0] * z0, O[nt][1] * z0);
            float2 v1 = make_float2(O[nt][2] * z1, O[nt][3] * z1);
            *(float2*)&g_attn[(size_t)(q0 + r0) * DMOD + col]     = v0;
            *(float2*)&g_attn[(size_t)(q0 + r0 + 8) * DMOD + col] = v1;
        }
    }
    if (blockIdx.x == 0 && tid == 0) g_Z0 = Zb[0];
}

// ---------------- bf16 tensor-core QKV projection GEMM ----------------
// C[8192x512] = A[8192x512]bf16 @ W[512x512]bf16 + bias, bf16 out.
// blockIdx.z selects (W, bias, out). 128x128 tile, K slices of 64, 8 warps.
__global__ __launch_bounds__(256)
void gemm_qkv(const __nv_bfloat16* __restrict__ A,
              const __nv_bfloat16* __restrict__ Wa, const __nv_bfloat16* __restrict__ Wb2, const __nv_bfloat16* __restrict__ Wc,
              const float* __restrict__ ba, const float* __restrict__ bb2, const float* __restrict__ bc,
              __nv_bfloat16* __restrict__ oa, __nv_bfloat16* __restrict__ ob, __nv_bfloat16* __restrict__ oc)
{
    extern __shared__ char smg[];
    uint32_t sb = (uint32_t)__cvta_generic_to_shared(smg);

    const __nv_bfloat16* W;
    const float* bias;
    __nv_bfloat16* out;
    if (blockIdx.z == 0)      { W = Wa;  bias = ba;  out = oa; }
    else if (blockIdx.z == 1) { W = Wb2; bias = bb2; out = ob; }
    else                      { W = Wc;  bias = bc;  out = oc; }

    const int tid  = threadIdx.x;
    const int wd   = tid >> 5;
    const int lane = tid & 31;
    const int r8   = lane & 7;
    const int jj   = lane >> 3;
    const int gid  = lane >> 2;
    const int tig  = lane & 3;
    const int wm   = wd >> 2;   // 0..1
    const int wn   = wd & 3;    // 0..3
    const int bm   = blockIdx.x * 128;
    const int bn   = blockIdx.y * 128;

    const int rP  = r8 + ((jj & 1) << 3);
    const int cP8 = jj >> 1;

    float acc[4][4][4];
#pragma unroll
    for (int mt = 0; mt < 4; mt++) {
#pragma unroll
        for (int nt = 0; nt < 4; nt++) {
#pragma unroll
            for (int q2 = 0; q2 < 4; q2++) { acc[mt][nt][q2] = 0.f; }
        }
    }

    // stage slice 0: A tile 128x64 (16KB) at 0/16384, W tile 64x128 (16KB) at 32768/49152
#pragma unroll
    for (int i = 0; i < 4; i++) {
        int idx = i * 256 + tid;
        int row = idx >> 3;
        int c16 = idx & 7;
        cpa16(sb + (uint32_t)(row * 128 + ((c16 ^ (row & 7)) << 4)),
              (const char*)(A + (size_t)(bm + row) * DMOD) + (size_t)c16 * 16);
    }
#pragma unroll
    for (int i = 0; i < 4; i++) {
        int idx = i * 256 + tid;
        int k = idx >> 4;
        int c16 = idx & 15;
        cpa16(sb + (uint32_t)(32768 + k * 256 + ((c16 ^ (k & 7)) << 4)),
              (const char*)(W + (size_t)k * DMOD + bn) + (size_t)c16 * 16);
    }
    cpcommit();

    for (int s = 0; s < 8; s++) {
        cpwait0();
        __syncthreads();
        if (s < 7) {
            int ns = s + 1;
            uint32_t ab = sb + (uint32_t)((ns & 1) * 16384);
            uint32_t wb = sb + (uint32_t)(32768 + (ns & 1) * 16384);
#pragma unroll
            for (int i = 0; i < 4; i++) {
                int idx = i * 256 + tid;
                int row = idx >> 3;
                int c16 = idx & 7;
                cpa16(ab + (uint32_t)(row * 128 + ((c16 ^ (row & 7)) << 4)),
                      (const char*)(A + (size_t)(bm + row) * DMOD + (size_t)ns * 64) + (size_t)c16 * 16);
            }
#pragma unroll
            for (int i = 0; i < 4; i++) {
                int idx = i * 256 + tid;
                int k = idx >> 4;
                int c16 = idx & 15;
                cpa16(wb + (uint32_t)(k * 256 + ((c16 ^ (k & 7)) << 4)),
                      (const char*)(W + (size_t)(ns * 64 + k) * DMOD + bn) + (size_t)c16 * 16);
            }
            cpcommit();
        }
        uint32_t sa = sb + (uint32_t)((s & 1) * 16384);
        uint32_t sw = sb + (uint32_t)(32768 + (s & 1) * 16384);
#pragma unroll
        for (int ks = 0; ks < 4; ks++) {
            uint32_t a0[4], a1[4], a2[4], a3[4];
            {
                int ck = ks * 2 + cP8;
                int rowA0 = wm * 64 + 0 * 16 + rP;
                int rowA1 = wm * 64 + 1 * 16 + rP;
                int rowA2 = wm * 64 + 2 * 16 + rP;
                int rowA3 = wm * 64 + 3 * 16 + rP;
                ldm4(a0[0], a0[1], a0[2], a0[3], sa + (uint32_t)(rowA0 * 128 + ((ck ^ (rowA0 & 7)) << 4)));
                ldm4(a1[0], a1[1], a1[2], a1[3], sa + (uint32_t)(rowA1 * 128 + ((ck ^ (rowA1 & 7)) << 4)));
                ldm4(a2[0], a2[1], a2[2], a2[3], sa + (uint32_t)(rowA2 * 128 + ((ck ^ (rowA2 & 7)) << 4)));
                ldm4(a3[0], a3[1], a3[2], a3[3], sa + (uint32_t)(rowA3 * 128 + ((ck ^ (rowA3 & 7)) << 4)));
            }
#pragma unroll
            for (int nt2 = 0; nt2 < 2; nt2++) {
                uint32_t b0, b1, b2, b3;
                int rv = ks * 16 + rP;
                int cv = wn * 4 + nt2 * 2 + cP8;
                ldm4t(b0, b1, b2, b3, sw + (uint32_t)(rv * 256 + ((cv ^ (rv & 7)) << 4)));
                mmab(acc[0][2*nt2  ][0], acc[0][2*nt2  ][1], acc[0][2*nt2  ][2], acc[0][2*nt2  ][3], a0[0], a0[1], a0[2], a0[3], b0, b1);
                mmab(acc[0][2*nt2+1][0], acc[0][2*nt2+1][1], acc[0][2*nt2+1][2], acc[0][2*nt2+1][3], a0[0], a0[1], a0[2], a0[3], b2, b3);
                mmab(acc[1][2*nt2  ][0], acc[1][2*nt2  ][1], acc[1][2*nt2  ][2], acc[1][2*nt2  ][3], a1[0], a1[1], a1[2], a1[3], b0, b1);
                mmab(acc[1][2*nt2+1][0], acc[1][2*nt2+1][1], acc[1][2*nt2+1][2], acc[1][2*nt2+1][3], a1[0], a1[1], a1[2], a1[3], b2, b3);
                mmab(acc[2][2*nt2  ][0], acc[2][2*nt2  ][1], acc[2][2*nt2  ][2], acc[2][2*nt2  ][3], a2[0], a2[1], a2[2], a2[3], b0, b1);
                mmab(acc[2][2*nt2+1][0], acc[2][2*nt2+1][1], acc[2][2*nt2+1][2], acc[2][2*nt2+1][3], a2[0], a2[1], a2[2], a2[3], b2, b3);
                mmab(acc[3][2*nt2  ][0], acc[3][2*nt2  ][1], acc[3][2*nt2  ][2], acc[3][2*nt2  ][3], a3[0], a3[1], a3[2], a3[3], b0, b1);
                mmab(acc[3][2*nt2+1][0], acc[3][2*nt2+1][1], acc[3][2*nt2+1][2], acc[3][2*nt2+1][3], a3[0], a3[1], a3[2], a3[3], b2, b3);
            }
        }
    }

#pragma unroll
    for (int mt = 0; mt < 4; mt++) {
        int row0 = bm + wm * 64 + mt * 16 + gid;
        int row1 = row0 + 8;
#pragma unroll
        for (int nt = 0; nt < 4; nt++) {
            int col = bn + wn * 32 + nt * 8 + tig * 2;
            float bx = bias[col];
            float by = bias[col + 1];
            *(__nv_bfloat162*)&out[(size_t)row0 * DMOD + col] = __floats2bfloat162_rn(acc[mt][nt][0] + bx, acc[mt][nt][1] + by);
            *(__nv_bfloat162*)&out[(size_t)row1 * DMOD + col] = __floats2bfloat162_rn(acc[mt][nt][2] + bx, acc[mt][nt][3] + by);
        }
    }
}

// fp32 -> bf16 convert (vectorized by 4)
__global__ void convf2b(const float* __restrict__ s, __nv_bfloat16* __restrict__ d, int n4)
{
    int i = blockIdx.x * blockDim.x + threadIdx.x;
    if (i < n4) {
        float4 v = ((const float4*)s)[i];
        ((__nv_bfloat162*)d)[2 * i]     = __floats2bfloat162_rn(v.x, v.y);
        ((__nv_bfloat162*)d)[2 * i + 1] = __floats2bfloat162_rn(v.z, v.w);
    }
}

// final projection: fp32 SIMT, out = attn @ Wo + bo + x
__global__ __launch_bounds__(256, 2)
void gemm512(const float* __restrict__ A, const float* __restrict__ B,
             const float* __restrict__ bias, const float* __restrict__ resid,
             float* __restrict__ C)
{
    __shared__ float As[2][8][132];
    __shared__ float Bs[2][8][128];
    const int tid  = threadIdx.x;
    const int bm   = blockIdx.x * 128;
    const int bn   = blockIdx.y * 128;
    const int arow = tid >> 1;
    const int ak   = (tid & 1) << 2;
    const int brow = tid >> 5;
    const int bcol = (tid & 31) << 2;
    const int ty   = tid >> 4;
    const int tx   = tid & 15;

    float acc[8][8];
#pragma unroll
    for (int i = 0; i < 8; i++) {
#pragma unroll
        for (int j2 = 0; j2 < 8; j2++) { acc[i][j2] = 0.f; }
    }

    const float* Ap = A + (size_t)(bm + arow) * DMOD + ak;
    const float* Bp = B + (size_t)brow * DMOD + bn + bcol;
    float4 av = *(const float4*)Ap;
    float4 bv = *(const float4*)Bp;
    As[0][ak + 0][arow] = av.x; As[0][ak + 1][arow] = av.y;
    As[0][ak + 2][arow] = av.z; As[0][ak + 3][arow] = av.w;
    *(float4*)&Bs[0][brow][bcol] = bv;
    __syncthreads();

    int buf = 0;
#pragma unroll 1
    for (int s = 0; s < 64; s++) {
        if (s < 63) {
            av = *(const float4*)(Ap + (s + 1) * 8);
            bv = *(const float4*)(Bp + (size_t)(s + 1) * 8 * DMOD);
        }
#pragma unroll
        for (int kt = 0; kt < 8; kt++) {
            float4 a0 = *(float4*)&As[buf][kt][ty * 4];
            float4 a1 = *(float4*)&As[buf][kt][64 + ty * 4];
            float4 b0 = *(float4*)&Bs[buf][kt][tx * 4];
            float4 b1 = *(float4*)&Bs[buf][kt][64 + tx * 4];
            float ar[8] = {a0.x, a0.y, a0.z, a0.w, a1.x, a1.y, a1.z, a1.w};
            float br[8] = {b0.x, b0.y, b0.z, b0.w, b1.x, b1.y, b1.z, b1.w};
#pragma unroll
            for (int i = 0; i < 8; i++) {
#pragma unroll
                for (int j2 = 0; j2 < 8; j2++) { acc[i][j2] += ar[i] * br[j2]; }
            }
        }
        if (s < 63) {
            int nb = buf ^ 1;
            As[nb][ak + 0][arow] = av.x; As[nb][ak + 1][arow] = av.y;
            As[nb][ak + 2][arow] = av.z; As[nb][ak + 3][arow] = av.w;
            *(float4*)&Bs[nb][brow][bcol] = bv;
            __syncthreads();
            buf = nb;
        }
    }

#pragma unroll
    for (int ih = 0; ih < 2; ih++) {
#pragma unroll
        for (int i = 0; i < 4; i++) {
            int row = bm + ih * 64 + ty * 4 + i;
#pragma unroll
            for (int jh = 0; jh < 2; jh++) {
                int col = bn + jh * 64 + tx * 4;
                float4 vv;
                vv.x = acc[ih * 4 + i][jh * 4 + 0] + bias[col + 0];
                vv.y = acc[ih * 4 + i][jh * 4 + 1] + bias[col + 1];
                vv.z = acc[ih * 4 + i][jh * 4 + 2] + bias[col + 2];
                vv.w = acc[ih * 4 + i][jh * 4 + 3] + bias[col + 3];
                float4 rr = *(const float4*)&resid[(size_t)row * DMOD + col];
                vv.x += rr.x; vv.y += rr.y; vv.z += rr.z; vv.w += rr.w;
                *(float4*)&C[(size_t)row * DMOD + col] = vv;
            }
        }
    }
}

__global__ void cls_kernel(float* __restrict__ out)
{
    int m = blockIdx.x * 256 + threadIdx.x;
    out[m] = g_cls[m] / g_Z0;
}

extern "C" void kernel_launch(void* const* d_in, const int* in_sizes, int n_in,
                              void* d_out, int out_size)
{
    const float* x  = (const float*)d_in[0];
    const float* Wq = (const float*)d_in[1];
    const float* bq = (const float*)d_in[2];
    const float* Wk = (const float*)d_in[3];
    const float* bk = (const float*)d_in[4];
    const float* Wv = (const float*)d_in[5];
    const float* bv = (const float*)d_in[6];
    const float* Wo = (const float*)d_in[7];
    const float* bo = (const float*)d_in[8];
    float* out = (float*)d_out;

    __nv_bfloat16* xb = 0;
    __nv_bfloat16* w0 = 0;
    __nv_bfloat16* w1 = 0;
    __nv_bfloat16* w2 = 0;
    __nv_bfloat16* qb = 0;
    __nv_bfloat16* kb = 0;
    __nv_bfloat16* vb = 0;
    float* attn = 0;
    cudaGetSymbolAddress((void**)&xb, g_xb);
    cudaGetSymbolAddress((void**)&w0, g_w0);
    cudaGetSymbolAddress((void**)&w1, g_w1);
    cudaGetSymbolAddress((void**)&w2, g_w2);
    cudaGetSymbolAddress((void**)&qb, g_qb);
    cudaGetSymbolAddress((void**)&kb, g_kb);
    cudaGetSymbolAddress((void**)&vb, g_vb);
    cudaGetSymbolAddress((void**)&attn, g_attn);

    cudaFuncSetAttribute(attn2, cudaFuncAttributeMaxDynamicSharedMemorySize, SM_TOTAL);
    cudaFuncSetAttribute(gemm_qkv, cudaFuncAttributeMaxDynamicSharedMemorySize, 65536);

    convf2b<<<4096, 256>>>(x, xb, NTOK * DMOD / 4);
    convf2b<<<256, 256>>>(Wq, w0, DMOD * DMOD / 4);
    convf2b<<<256, 256>>>(Wk, w1, DMOD * DMOD / 4);
    convf2b<<<256, 256>>>(Wv, w2, DMOD * DMOD / 4);

    dim3 gq(64, 4, 3);
    gemm_qkv<<<gq, 256, 65536>>>(xb, w0, w1, w2, bq, bk, bv, qb, kb, vb);

    attn2<<<256, 512, SM_TOTAL>>>();

    dim3 gg(64, 4);
    gemm512<<<gg, 256>>>(attn, Wo, bo, x, out);
    cls_kernel<<<32, 256>>>(out + (size_t)NTOK * DMOD);
}

// round 10
// speedup vs baseline: 7.6030x; 1.3127x over previous
#include <cuda_runtime.h>
#include <cuda_bf16.h>
#include <cstdint>

constexpr int NTOK = 8192;
constexpr int DMOD = 512;

__device__ __nv_bfloat16 g_xb[NTOK * DMOD];
__device__ __nv_bfloat16 g_w0[DMOD * DMOD];
__device__ __nv_bfloat16 g_w1[DMOD * DMOD];
__device__ __nv_bfloat16 g_w2[DMOD * DMOD];
__device__ __nv_bfloat16 g_w3[DMOD * DMOD];
__device__ __nv_bfloat16 g_qb[NTOK * DMOD];
__device__ __nv_bfloat16 g_kb[NTOK * DMOD];
__device__ __nv_bfloat16 g_vb[NTOK * DMOD];
__device__ __nv_bfloat16 g_ab[NTOK * DMOD];
__device__ float g_cls[NTOK];
__device__ float g_Z0;

// attn2 smem: Q[0,32K) E[32K,64K) KV 2x64K [64K,192K) srow[+512) Zb[+128)
constexpr int EOFF = 32768;
constexpr int SOFF = 65536;
constexpr int ROFF = 196608;
constexpr int ZOFF = 197120;
constexpr int SM_TOTAL = 197248;

__device__ __forceinline__ void ldm4(uint32_t &r0, uint32_t &r1, uint32_t &r2, uint32_t &r3, uint32_t ad)
{
    asm volatile("ldmatrix.sync.aligned.m8n8.x4.shared.b16 {%0,%1,%2,%3},[%4];"
                 : "=r"(r0), "=r"(r1), "=r"(r2), "=r"(r3) : "r"(ad));
}
__device__ __forceinline__ void ldm4t(uint32_t &r0, uint32_t &r1, uint32_t &r2, uint32_t &r3, uint32_t ad)
{
    asm volatile("ldmatrix.sync.aligned.m8n8.x4.trans.shared.b16 {%0,%1,%2,%3},[%4];"
                 : "=r"(r0), "=r"(r1), "=r"(r2), "=r"(r3) : "r"(ad));
}
__device__ __forceinline__ void mmab(float &c0, float &c1, float &c2, float &c3,
                                     uint32_t a0, uint32_t a1, uint32_t a2, uint32_t a3,
                                     uint32_t b0, uint32_t b1)
{
    asm volatile("mma.sync.aligned.m16n8k16.row.col.f32.bf16.bf16.f32 "
                 "{%0,%1,%2,%3},{%4,%5,%6,%7},{%8,%9},{%0,%1,%2,%3};"
                 : "+f"(c0), "+f"(c1), "+f"(c2), "+f"(c3)
                 : "r"(a0), "r"(a1), "r"(a2), "r"(a3), "r"(b0), "r"(b1));
}
__device__ __forceinline__ void cpa16(uint32_t s, const void* g)
{
    asm volatile("cp.async.cg.shared.global [%0],[%1],16;" :: "r"(s), "l"(g));
}
__device__ __forceinline__ void cpcommit() { asm volatile("cp.async.commit_group;"); }
__device__ __forceinline__ void cpwait0()  { asm volatile("cp.async.wait_group 0;"); }

// K stage: 128 keys x 256 d-half (64KB), rows 512B, swizzled
__device__ __forceinline__ void stageK(uint32_t buf, int c, int kb, int dh, int tid)
{
#pragma unroll
    for (int i = 0; i < 16; i++) {
        int idx = i * 256 + tid;
        int row = idx >> 5;
        int c16 = idx & 31;
        cpa16(buf + (uint32_t)(row * 512 + ((c16 ^ (row & 7)) << 4)),
              (const char*)(g_kb + (size_t)(c * 512 + kb * 128 + row) * DMOD) + dh * 512 + c16 * 16);
    }
}
// V stage: 64 keys x 512 d (64KB), rows 1024B, swizzled
__device__ __forceinline__ void stageV(uint32_t buf, int c, int kv, int tid)
{
#pragma unroll
    for (int i = 0; i < 16; i++) {
        int idx = i * 256 + tid;
        int row = idx >> 6;
        int c16 = idx & 63;
        cpa16(buf + (uint32_t)(row * 1024 + ((c16 ^ (row & 7)) << 4)),
              (const char*)(g_vb + (size_t)(c * 512 + kv * 64 + row) * DMOD) + c16 * 16);
    }
}

__global__ __launch_bounds__(256)
void attn2()
{
    extern __shared__ char sm[];
    uint32_t sb = (uint32_t)__cvta_generic_to_shared(sm);
    float* srow = (float*)(sm + ROFF);
    float* Zb   = (float*)(sm + ZOFF);

    const int tid  = threadIdx.x;
    const int wd   = tid >> 5;
    const int lane = tid & 31;
    const int r8   = lane & 7;
    const int jj   = lane >> 3;
    const int gid  = lane >> 2;
    const int tig  = lane & 3;
    const int wm   = wd >> 2;   // 0..1 (m16 groups)
    const int wn   = wd & 3;    // 0..3 (n32-key groups)
    const int q0   = blockIdx.x << 5;
    const float SC = 0.044194173824159216f;  // 1/sqrt(512)

    if (tid < 32)  Zb[tid] = 0.f;
    if (tid < 128) srow[tid] = 0.f;

    // Q tile (32x512 bf16) -> smem swizzled, rows 1024B
    const char* qg = (const char*)(g_qb + (size_t)q0 * DMOD);
#pragma unroll
    for (int i = 0; i < 8; i++) {
        int idx = i * 256 + tid;
        int row = idx >> 6;
        int c16 = idx & 63;
        *(uint4*)(sm + row * 1024 + ((c16 ^ (row & 7)) << 4)) =
            *(const uint4*)(qg + (size_t)row * 1024 + (size_t)c16 * 16);
    }

    const int rA  = wm * 16 + r8 + ((jj & 1) << 3);
    const int cA8 = jj >> 1;
    const int rB0 = wn * 32 + r8 + ((jj >> 1) << 3);
    const int cB8 = jj & 1;
    const int rP  = r8 + ((jj & 1) << 3);
    const int cP8 = jj >> 1;

    float O[2][8][4];
#pragma unroll
    for (int x1 = 0; x1 < 2; x1++)
#pragma unroll
        for (int x2 = 0; x2 < 8; x2++)
#pragma unroll
            for (int x3 = 0; x3 < 4; x3++) { O[x1][x2][x3] = 0.f; }

    int pb = 0;
    stageK(sb + SOFF, 0, 0, 0, tid);
    cpcommit();

    for (int c = 0; c < 16; c++) {
        // ======== QK: 4 kb-blocks of 128 keys, each over 2 d-halves ========
        for (int kb = 0; kb < 4; kb++) {
            float S[4][4];
#pragma unroll
            for (int f = 0; f < 4; f++)
#pragma unroll
                for (int t = 0; t < 4; t++) { S[f][t] = 0.f; }

            for (int dh = 0; dh < 2; dh++) {
                cpwait0();
                __syncthreads();
                uint32_t nb = sb + SOFF + ((uint32_t)(pb ^ 1) << 16);
                if (dh == 0)      stageK(nb, c, kb, 1, tid);
                else if (kb < 3)  stageK(nb, c, kb + 1, 0, tid);
                else              stageV(nb, c, 0, tid);
                cpcommit();
                uint32_t stg = sb + SOFF + ((uint32_t)pb << 16);

#pragma unroll 4
                for (int ks = 0; ks < 16; ks++) {
                    uint32_t a0, a1, a2, a3;
                    int cq = dh * 32 + ks * 2 + cA8;
                    ldm4(a0, a1, a2, a3, sb + (uint32_t)(rA * 1024 + ((cq ^ (rA & 7)) << 4)));
                    uint32_t b0, b1, b2, b3;
                    int ck = ks * 2 + cB8;
                    ldm4(b0, b1, b2, b3, stg + (uint32_t)(rB0 * 512 + ((ck ^ (rB0 & 7)) << 4)));
                    mmab(S[0][0], S[0][1], S[0][2], S[0][3], a0, a1, a2, a3, b0, b1);
                    mmab(S[1][0], S[1][1], S[1][2], S[1][3], a0, a1, a2, a3, b2, b3);
                    int rB1 = rB0 + 16;
                    ldm4(b0, b1, b2, b3, stg + (uint32_t)(rB1 * 512 + ((ck ^ (rB1 & 7)) << 4)));
                    mmab(S[2][0], S[2][1], S[2][2], S[2][3], a0, a1, a2, a3, b0, b1);
                    mmab(S[3][0], S[3][1], S[3][2], S[3][3], a0, a1, a2, a3, b2, b3);
                }
                pb ^= 1;
            }
            // E1 = exp(S*SC) -> smem bf16, partial row sums
            float p0 = 0.f, p1 = 0.f;
            int rw0 = wm * 16 + gid;
            int rw1 = rw0 + 8;
#pragma unroll
            for (int f = 0; f < 4; f++) {
                float e0 = __expf(S[f][0] * SC), e1 = __expf(S[f][1] * SC);
                float e2 = __expf(S[f][2] * SC), e3 = __expf(S[f][3] * SC);
                p0 += e0 + e1; p1 += e2 + e3;
                int key = kb * 128 + wn * 32 + f * 8 + tig * 2;
                *(__nv_bfloat162*)(sm + EOFF + rw0 * 1024 + (((key >> 3) ^ (rw0 & 7)) << 4) + ((key & 7) << 1)) = __floats2bfloat162_rn(e0, e1);
                *(__nv_bfloat162*)(sm + EOFF + rw1 * 1024 + (((key >> 3) ^ (rw1 & 7)) << 4) + ((key & 7) << 1)) = __floats2bfloat162_rn(e2, e3);
            }
            p0 += __shfl_xor_sync(0xffffffffu, p0, 1);
            p0 += __shfl_xor_sync(0xffffffffu, p0, 2);
            p1 += __shfl_xor_sync(0xffffffffu, p1, 1);
            p1 += __shfl_xor_sync(0xffffffffu, p1, 2);
            if (tig == 0) {
                srow[wn * 32 + wm * 16 + gid]     += p0;
                srow[wn * 32 + wm * 16 + gid + 8] += p1;
            }
        }
        __syncthreads();

        // ======== chunk softmax -> E2 in place, Z accum, cls ========
        {
            int row = tid >> 3;
            int seg = tid & 7;
            float rinv = 1.f / (srow[row] + srow[32 + row] + srow[64 + row] + srow[96 + row]);
            float z = 0.f;
#pragma unroll
            for (int i = 0; i < 8; i++) {
                int c16 = seg * 8 + i;
                uint32_t* p = (uint32_t*)(sm + EOFF + row * 1024 + ((c16 ^ (row & 7)) << 4));
#pragma unroll
                for (int qq = 0; qq < 4; qq++) {
                    float2 fv = __bfloat1622float2(*(__nv_bfloat162*)(p + qq));
                    float u0 = __expf(fv.x * rinv);
                    float u1 = __expf(fv.y * rinv);
                    z += u0 + u1;
                    *(__nv_bfloat162*)(p + qq) = __floats2bfloat162_rn(u0, u1);
                    if (blockIdx.x == 0 && row == 0) {
                        int col = c16 * 8 + qq * 2;
                        g_cls[c * 512 + col]     = u0;
                        g_cls[c * 512 + col + 1] = u1;
                    }
                }
            }
            z += __shfl_xor_sync(0xffffffffu, z, 1);
            z += __shfl_xor_sync(0xffffffffu, z, 2);
            z += __shfl_xor_sync(0xffffffffu, z, 4);
            if (seg == 0) Zb[row] += z;
        }

        // ======== PV: 8 stages of 64 keys x full d, warp m32n64 ========
        for (int kv = 0; kv < 8; kv++) {
            cpwait0();
            __syncthreads();
            if (kv == 0 && tid < 128) srow[tid] = 0.f;
            uint32_t nb = sb + SOFF + ((uint32_t)(pb ^ 1) << 16);
            if (kv < 7)      { stageV(nb, c, kv + 1, tid); }
            else if (c < 15) { stageK(nb, c + 1, 0, 0, tid); }
            cpcommit();
            uint32_t stg = sb + SOFF + ((uint32_t)pb << 16);
#pragma unroll
            for (int ks = 0; ks < 4; ks++) {
                uint32_t a00, a01, a02, a03, a10, a11, a12, a13;
                int ce  = kv * 8 + ks * 2 + cP8;
                int ra1 = 16 + rP;
                ldm4(a00, a01, a02, a03, sb + (uint32_t)(EOFF + rP  * 1024 + ((ce ^ (rP  & 7)) << 4)));
                ldm4(a10, a11, a12, a13, sb + (uint32_t)(EOFF + ra1 * 1024 + ((ce ^ (ra1 & 7)) << 4)));
                int rv = ks * 16 + rP;
#pragma unroll
                for (int nt = 0; nt < 4; nt++) {
                    uint32_t b0, b1, b2, b3;
                    int cv = wd * 8 + nt * 2 + cP8;
                    ldm4t(b0, b1, b2, b3, stg + (uint32_t)(rv * 1024 + ((cv ^ (rv & 7)) << 4)));
                    mmab(O[0][2*nt  ][0], O[0][2*nt  ][1], O[0][2*nt  ][2], O[0][2*nt  ][3], a00, a01, a02, a03, b0, b1);
                    mmab(O[0][2*nt+1][0], O[0][2*nt+1][1], O[0][2*nt+1][2], O[0][2*nt+1][3], a00, a01, a02, a03, b2, b3);
                    mmab(O[1][2*nt  ][0], O[1][2*nt  ][1], O[1][2*nt  ][2], O[1][2*nt  ][3], a10, a11, a12, a13, b0, b1);
                    mmab(O[1][2*nt+1][0], O[1][2*nt+1][1], O[1][2*nt+1][2], O[1][2*nt+1][3], a10, a11, a12, a13, b2, b3);
                }
            }
            pb ^= 1;
        }
    }
    __syncthreads();

    // normalize + store bf16
#pragma unroll
    for (int mt = 0; mt < 2; mt++) {
        int r0 = mt * 16 + gid;
        float z0 = 1.f / Zb[r0];
        float z1 = 1.f / Zb[r0 + 8];
#pragma unroll
        for (int nt = 0; nt < 8; nt++) {
            int col = wd * 64 + nt * 8 + tig * 2;
            *(__nv_bfloat162*)&g_ab[(size_t)(q0 + r0) * DMOD + col]     = __floats2bfloat162_rn(O[mt][nt][0] * z0, O[mt][nt][1] * z0);
            *(__nv_bfloat162*)&g_ab[(size_t)(q0 + r0 + 8) * DMOD + col] = __floats2bfloat162_rn(O[mt][nt][2] * z1, O[mt][nt][3] * z1);
        }
    }
    if (blockIdx.x == 0 && tid == 0) g_Z0 = Zb[0];
}

// ---------------- bf16 tensor-core QKV projection GEMM ----------------
__global__ __launch_bounds__(256)
void gemm_qkv(const __nv_bfloat16* __restrict__ A,
              const __nv_bfloat16* __restrict__ Wa, const __nv_bfloat16* __restrict__ Wb2, const __nv_bfloat16* __restrict__ Wc,
              const float* __restrict__ ba, const float* __restrict__ bb2, const float* __restrict__ bc,
              __nv_bfloat16* __restrict__ oa, __nv_bfloat16* __restrict__ ob, __nv_bfloat16* __restrict__ oc)
{
    extern __shared__ char smg[];
    uint32_t sb = (uint32_t)__cvta_generic_to_shared(smg);

    const __nv_bfloat16* W;
    const float* bias;
    __nv_bfloat16* out;
    if (blockIdx.z == 0)      { W = Wa;  bias = ba;  out = oa; }
    else if (blockIdx.z == 1) { W = Wb2; bias = bb2; out = ob; }
    else                      { W = Wc;  bias = bc;  out = oc; }

    const int tid  = threadIdx.x;
    const int wd   = tid >> 5;
    const int lane = tid & 31;
    const int r8   = lane & 7;
    const int jj   = lane >> 3;
    const int gid  = lane >> 2;
    const int tig  = lane & 3;
    const int wm   = wd >> 2;
    const int wn   = wd & 3;
    const int bm   = blockIdx.x * 128;
    const int bn   = blockIdx.y * 128;
    const int rP   = r8 + ((jj & 1) << 3);
    const int cP8  = jj >> 1;

    float acc[4][4][4];
#pragma unroll
    for (int mt = 0; mt < 4; mt++)
#pragma unroll
        for (int nt = 0; nt < 4; nt++)
#pragma unroll
            for (int q2 = 0; q2 < 4; q2++) { acc[mt][nt][q2] = 0.f; }

#pragma unroll
    for (int i = 0; i < 4; i++) {
        int idx = i * 256 + tid;
        int row = idx >> 3;
        int c16 = idx & 7;
        cpa16(sb + (uint32_t)(row * 128 + ((c16 ^ (row & 7)) << 4)),
              (const char*)(A + (size_t)(bm + row) * DMOD) + (size_t)c16 * 16);
    }
#pragma unroll
    for (int i = 0; i < 4; i++) {
        int idx = i * 256 + tid;
        int k = idx >> 4;
        int c16 = idx & 15;
        cpa16(sb + (uint32_t)(32768 + k * 256 + ((c16 ^ (k & 7)) << 4)),
              (const char*)(W + (size_t)k * DMOD + bn) + (size_t)c16 * 16);
    }
    cpcommit();

    for (int s = 0; s < 8; s++) {
        cpwait0();
        __syncthreads();
        if (s < 7) {
            int ns = s + 1;
            uint32_t ab = sb + (uint32_t)((ns & 1) * 16384);
            uint32_t wb = sb + (uint32_t)(32768 + (ns & 1) * 16384);
#pragma unroll
            for (int i = 0; i < 4; i++) {
                int idx = i * 256 + tid;
                int row = idx >> 3;
                int c16 = idx & 7;
                cpa16(ab + (uint32_t)(row * 128 + ((c16 ^ (row & 7)) << 4)),
                      (const char*)(A + (size_t)(bm + row) * DMOD + (size_t)ns * 64) + (size_t)c16 * 16);
            }
#pragma unroll
            for (int i = 0; i < 4; i++) {
                int idx = i * 256 + tid;
                int k = idx >> 4;
                int c16 = idx & 15;
                cpa16(wb + (uint32_t)(k * 256 + ((c16 ^ (k & 7)) << 4)),
                      (const char*)(W + (size_t)(ns * 64 + k) * DMOD + bn) + (size_t)c16 * 16);
            }
            cpcommit();
        }
        uint32_t sa = sb + (uint32_t)((s & 1) * 16384);
        uint32_t sw = sb + (uint32_t)(32768 + (s & 1) * 16384);
#pragma unroll
        for (int ks = 0; ks < 4; ks++) {
            uint32_t am[4][4];
            int ck = ks * 2 + cP8;
#pragma unroll
            for (int mt = 0; mt < 4; mt++) {
                int rowA = wm * 64 + mt * 16 + rP;
                ldm4(am[mt][0], am[mt][1], am[mt][2], am[mt][3], sa + (uint32_t)(rowA * 128 + ((ck ^ (rowA & 7)) << 4)));
            }
#pragma unroll
            for (int nt2 = 0; nt2 < 2; nt2++) {
                uint32_t b0, b1, b2, b3;
                int rv = ks * 16 + rP;
                int cv = wn * 4 + nt2 * 2 + cP8;
                ldm4t(b0, b1, b2, b3, sw + (uint32_t)(rv * 256 + ((cv ^ (rv & 7)) << 4)));
#pragma unroll
                for (int mt = 0; mt < 4; mt++) {
                    mmab(acc[mt][2*nt2  ][0], acc[mt][2*nt2  ][1], acc[mt][2*nt2  ][2], acc[mt][2*nt2  ][3], am[mt][0], am[mt][1], am[mt][2], am[mt][3], b0, b1);
                    mmab(acc[mt][2*nt2+1][0], acc[mt][2*nt2+1][1], acc[mt][2*nt2+1][2], acc[mt][2*nt2+1][3], am[mt][0], am[mt][1], am[mt][2], am[mt][3], b2, b3);
                }
            }
        }
    }

#pragma unroll
    for (int mt = 0; mt < 4; mt++) {
        int row0 = bm + wm * 64 + mt * 16 + gid;
        int row1 = row0 + 8;
#pragma unroll
        for (int nt = 0; nt < 4; nt++) {
            int col = bn + wn * 32 + nt * 8 + tig * 2;
            float bx = bias[col];
            float by = bias[col + 1];
            *(__nv_bfloat162*)&out[(size_t)row0 * DMOD + col] = __floats2bfloat162_rn(acc[mt][nt][0] + bx, acc[mt][nt][1] + by);
            *(__nv_bfloat162*)&out[(size_t)row1 * DMOD + col] = __floats2bfloat162_rn(acc[mt][nt][2] + bx, acc[mt][nt][3] + by);
        }
    }
}

// ------------- bf16 output projection GEMM: out = A@W + bias + resid (fp32) -------------
__global__ __launch_bounds__(256)
void gemm_out(const __nv_bfloat16* __restrict__ A, const __nv_bfloat16* __restrict__ W,
              const float* __restrict__ bias, const float* __restrict__ resid,
              float* __restrict__ out)
{
    extern __shared__ char smg[];
    uint32_t sb = (uint32_t)__cvta_generic_to_shared(smg);

    const int tid  = threadIdx.x;
    const int wd   = tid >> 5;
    const int lane = tid & 31;
    const int r8   = lane & 7;
    const int jj   = lane >> 3;
    const int gid  = lane >> 2;
    const int tig  = lane & 3;
    const int wm   = wd >> 2;
    const int wn   = wd & 3;
    const int bm   = blockIdx.x * 128;
    const int bn   = blockIdx.y * 128;
    const int rP   = r8 + ((jj & 1) << 3);
    const int cP8  = jj >> 1;

    float acc[4][4][4];
#pragma unroll
    for (int mt = 0; mt < 4; mt++)
#pragma unroll
        for (int nt = 0; nt < 4; nt++)
#pragma unroll
            for (int q2 = 0; q2 < 4; q2++) { acc[mt][nt][q2] = 0.f; }

#pragma unroll
    for (int i = 0; i < 4; i++) {
        int idx = i * 256 + tid;
        int row = idx >> 3;
        int c16 = idx & 7;
        cpa16(sb + (uint32_t)(row * 128 + ((c16 ^ (row & 7)) << 4)),
              (const char*)(A + (size_t)(bm + row) * DMOD) + (size_t)c16 * 16);
    }
#pragma unroll
    for (int i = 0; i < 4; i++) {
        int idx = i * 256 + tid;
        int k = idx >> 4;
        int c16 = idx & 15;
        cpa16(sb + (uint32_t)(32768 + k * 256 + ((c16 ^ (k & 7)) << 4)),
              (const char*)(W + (size_t)k * DMOD + bn) + (size_t)c16 * 16);
    }
    cpcommit();

    for (int s = 0; s < 8; s++) {
        cpwait0();
        __syncthreads();
        if (s < 7) {
            int ns = s + 1;
            uint32_t ab = sb + (uint32_t)((ns & 1) * 16384);
            uint32_t wb = sb + (uint32_t)(32768 + (ns & 1) * 16384);
#pragma unroll
            for (int i = 0; i < 4; i++) {
                int idx = i * 256 + tid;
                int row = idx >> 3;
                int c16 = idx & 7;
                cpa16(ab + (uint32_t)(row * 128 + ((c16 ^ (row & 7)) << 4)),
                      (const char*)(A + (size_t)(bm + row) * DMOD + (size_t)ns * 64) + (size_t)c16 * 16);
            }
#pragma unroll
            for (int i = 0; i < 4; i++) {
                int idx = i * 256 + tid;
                int k = idx >> 4;
                int c16 = idx & 15;
                cpa16(wb + (uint32_t)(k * 256 + ((c16 ^ (k & 7)) << 4)),
                      (const char*)(W + (size_t)(ns * 64 + k) * DMOD + bn) + (size_t)c16 * 16);
            }
            cpcommit();
        }
        uint32_t sa = sb + (uint32_t)((s & 1) * 16384);
        uint32_t sw = sb + (uint32_t)(32768 + (s & 1) * 16384);
#pragma unroll
        for (int ks = 0; ks < 4; ks++) {
            uint32_t am[4][4];
            int ck = ks * 2 + cP8;
#pragma unroll
            for (int mt = 0; mt < 4; mt++) {
                int rowA = wm * 64 + mt * 16 + rP;
                ldm4(am[mt][0], am[mt][1], am[mt][2], am[mt][3], sa + (uint32_t)(rowA * 128 + ((ck ^ (rowA & 7)) << 4)));
            }
#pragma unroll
            for (int nt2 = 0; nt2 < 2; nt2++) {
                uint32_t b0, b1, b2, b3;
                int rv = ks * 16 + rP;
                int cv = wn * 4 + nt2 * 2 + cP8;
                ldm4t(b0, b1, b2, b3, sw + (uint32_t)(rv * 256 + ((cv ^ (rv & 7)) << 4)));
#pragma unroll
                for (int mt = 0; mt < 4; mt++) {
                    mmab(acc[mt][2*nt2  ][0], acc[mt][2*nt2  ][1], acc[mt][2*nt2  ][2], acc[mt][2*nt2  ][3], am[mt][0], am[mt][1], am[mt][2], am[mt][3], b0, b1);
                    mmab(acc[mt][2*nt2+1][0], acc[mt][2*nt2+1][1], acc[mt][2*nt2+1][2], acc[mt][2*nt2+1][3], am[mt][0], am[mt][1], am[mt][2], am[mt][3], b2, b3);
                }
            }
        }
    }

#pragma unroll
    for (int mt = 0; mt < 4; mt++) {
        int row0 = bm + wm * 64 + mt * 16 + gid;
        int row1 = row0 + 8;
#pragma unroll
        for (int nt = 0; nt < 4; nt++) {
            int col = bn + wn * 32 + nt * 8 + tig * 2;
            float bx = bias[col];
            float by = bias[col + 1];
            float2 ra = *(const float2*)&resid[(size_t)row0 * DMOD + col];
            float2 rb = *(const float2*)&resid[(size_t)row1 * DMOD + col];
            float2 v0 = make_float2(acc[mt][nt][0] + bx + ra.x, acc[mt][nt][1] + by + ra.y);
            float2 v1 = make_float2(acc[mt][nt][2] + bx + rb.x, acc[mt][nt][3] + by + rb.y);
            *(float2*)&out[(size_t)row0 * DMOD + col] = v0;
            *(float2*)&out[(size_t)row1 * DMOD + col] = v1;
        }
    }
}

__global__ void convf2b(const float* __restrict__ s, __nv_bfloat16* __restrict__ d, int n4)
{
    int i = blockIdx.x * blockDim.x + threadIdx.x;
    if (i < n4) {
        float4 v = ((const float4*)s)[i];
        ((__nv_bfloat162*)d)[2 * i]     = __floats2bfloat162_rn(v.x, v.y);
        ((__nv_bfloat162*)d)[2 * i + 1] = __floats2bfloat162_rn(v.z, v.w);
    }
}

__global__ void cls_kernel(float* __restrict__ out)
{
    int m = blockIdx.x * 256 + threadIdx.x;
    out[m] = g_cls[m] / g_Z0;
}

extern "C" void kernel_launch(void* const* d_in, const int* in_sizes, int n_in,
                              void* d_out, int out_size)
{
    const float* x  = (const float*)d_in[0];
    const float* Wq = (const float*)d_in[1];
    const float* bq = (const float*)d_in[2];
    const float* Wk = (const float*)d_in[3];
    const float* bk = (const float*)d_in[4];
    const float* Wv = (const float*)d_in[5];
    const float* bv = (const float*)d_in[6];
    const float* Wo = (const float*)d_in[7];
    const float* bo = (const float*)d_in[8];
    float* out = (float*)d_out;

    __nv_bfloat16 *xb = 0, *w0 = 0, *w1 = 0, *w2 = 0, *w3 = 0, *qb = 0, *kb = 0, *vb = 0, *ab = 0;
    cudaGetSymbolAddress((void**)&xb, g_xb);
    cudaGetSymbolAddress((void**)&w0, g_w0);
    cudaGetSymbolAddress((void**)&w1, g_w1);
    cudaGetSymbolAddress((void**)&w2, g_w2);
    cudaGetSymbolAddress((void**)&w3, g_w3);
    cudaGetSymbolAddress((void**)&qb, g_qb);
    cudaGetSymbolAddress((void**)&kb, g_kb);
    cudaGetSymbolAddress((void**)&vb, g_vb);
    cudaGetSymbolAddress((void**)&ab, g_ab);

    cudaFuncSetAttribute(attn2, cudaFuncAttributeMaxDynamicSharedMemorySize, SM_TOTAL);
    cudaFuncSetAttribute(gemm_qkv, cudaFuncAttributeMaxDynamicSharedMemorySize, 65536);
    cudaFuncSetAttribute(gemm_out, cudaFuncAttributeMaxDynamicSharedMemorySize, 65536);

    convf2b<<<4096, 256>>>(x, xb, NTOK * DMOD / 4);
    convf2b<<<256, 256>>>(Wq, w0, DMOD * DMOD / 4);
    convf2b<<<256, 256>>>(Wk, w1, DMOD * DMOD / 4);
    convf2b<<<256, 256>>>(Wv, w2, DMOD * DMOD / 4);
    convf2b<<<256, 256>>>(Wo, w3, DMOD * DMOD / 4);

    dim3 gq(64, 4, 3);
    gemm_qkv<<<gq, 256, 65536>>>(xb, w0, w1, w2, bq, bk, bv, qb, kb, vb);

    attn2<<<256, 256, SM_TOTAL>>>();

    dim3 gg(64, 4);
    gemm_out<<<gg, 256, 65536>>>(ab, w3, bo, x, out);
    cls_kernel<<<32, 256>>>(out + (size_t)NTOK * DMOD);
}

// round 11
// speedup vs baseline: 8.7436x; 1.1500x over previous
#include <cuda_runtime.h>
#include <cuda_bf16.h>
#include <cstdint>

constexpr int NTOK = 8192;
constexpr int DMOD = 512;

__device__ __nv_bfloat16 g_xb[NTOK * DMOD];
__device__ __nv_bfloat16 g_w0[DMOD * DMOD];
__device__ __nv_bfloat16 g_w1[DMOD * DMOD];
__device__ __nv_bfloat16 g_w2[DMOD * DMOD];
__device__ __nv_bfloat16 g_w3[DMOD * DMOD];
__device__ __nv_bfloat16 g_qb[NTOK * DMOD];
__device__ __nv_bfloat16 g_kb[NTOK * DMOD];
__device__ __nv_bfloat16 g_vb[NTOK * DMOD];
__device__ __nv_bfloat16 g_ab[NTOK * DMOD];
__device__ float g_cls[NTOK];
__device__ float g_Z0;

// attn2 smem: Q[0,32K) E[32K,64K) KV 2x64K [64K,192K) srow[192K,+1K) Zb[+128)
constexpr int EOFF = 32768;
constexpr int SOFF = 65536;
constexpr int ROFF = 196608;
constexpr int ZOFF = 197632;
constexpr int SM_TOTAL = 197760;

__device__ __forceinline__ void ldm4(uint32_t &r0, uint32_t &r1, uint32_t &r2, uint32_t &r3, uint32_t ad)
{
    asm volatile("ldmatrix.sync.aligned.m8n8.x4.shared.b16 {%0,%1,%2,%3},[%4];"
                 : "=r"(r0), "=r"(r1), "=r"(r2), "=r"(r3) : "r"(ad));
}
__device__ __forceinline__ void ldm4t(uint32_t &r0, uint32_t &r1, uint32_t &r2, uint32_t &r3, uint32_t ad)
{
    asm volatile("ldmatrix.sync.aligned.m8n8.x4.trans.shared.b16 {%0,%1,%2,%3},[%4];"
                 : "=r"(r0), "=r"(r1), "=r"(r2), "=r"(r3) : "r"(ad));
}
__device__ __forceinline__ void mmab(float &c0, float &c1, float &c2, float &c3,
                                     uint32_t a0, uint32_t a1, uint32_t a2, uint32_t a3,
                                     uint32_t b0, uint32_t b1)
{
    asm volatile("mma.sync.aligned.m16n8k16.row.col.f32.bf16.bf16.f32 "
                 "{%0,%1,%2,%3},{%4,%5,%6,%7},{%8,%9},{%0,%1,%2,%3};"
                 : "+f"(c0), "+f"(c1), "+f"(c2), "+f"(c3)
                 : "r"(a0), "r"(a1), "r"(a2), "r"(a3), "r"(b0), "r"(b1));
}
__device__ __forceinline__ void cpa16(uint32_t s, const void* g)
{
    asm volatile("cp.async.cg.shared.global [%0],[%1],16;" :: "r"(s), "l"(g));
}
__device__ __forceinline__ void cpcommit() { asm volatile("cp.async.commit_group;"); }
__device__ __forceinline__ void cpwait0()  { asm volatile("cp.async.wait_group 0;"); }

// K stage: 256 keys x 128 d-quarter (64KB), rows 256B, swizzled
__device__ __forceinline__ void stageK(uint32_t buf, int c, int kh, int dq, int tid)
{
#pragma unroll
    for (int i = 0; i < 16; i++) {
        int idx = i * 256 + tid;
        int row = idx >> 4;
        int c16 = idx & 15;
        cpa16(buf + (uint32_t)(row * 256 + ((c16 ^ (row & 7)) << 4)),
              (const char*)(g_kb + (size_t)(c * 512 + kh * 256 + row) * DMOD) + dq * 256 + c16 * 16);
    }
}
// V stage: 64 keys x 512 d (64KB), rows 1024B, swizzled
__device__ __forceinline__ void stageV(uint32_t buf, int c, int kv, int tid)
{
#pragma unroll
    for (int i = 0; i < 16; i++) {
        int idx = i * 256 + tid;
        int row = idx >> 6;
        int c16 = idx & 63;
        cpa16(buf + (uint32_t)(row * 1024 + ((c16 ^ (row & 7)) << 4)),
              (const char*)(g_vb + (size_t)(c * 512 + kv * 64 + row) * DMOD) + c16 * 16);
    }
}

__global__ __launch_bounds__(256)
void attn2()
{
    extern __shared__ char sm[];
    uint32_t sb = (uint32_t)__cvta_generic_to_shared(sm);
    float* srow = (float*)(sm + ROFF);
    float* Zb   = (float*)(sm + ZOFF);

    const int tid  = threadIdx.x;
    const int wd   = tid >> 5;
    const int lane = tid & 31;
    const int r8   = lane & 7;
    const int jj   = lane >> 3;
    const int gid  = lane >> 2;
    const int tig  = lane & 3;
    const int wn   = wd;           // QK: 32-key group within 256-key block; PV: 64-col group
    const int q0   = blockIdx.x << 5;
    const float SC = 0.044194173824159216f;  // 1/sqrt(512)

    if (tid < 32) Zb[tid] = 0.f;
    srow[tid] = 0.f;

    // Q tile (32x512 bf16) -> smem swizzled, rows 1024B
    const char* qg = (const char*)(g_qb + (size_t)q0 * DMOD);
#pragma unroll
    for (int i = 0; i < 8; i++) {
        int idx = i * 256 + tid;
        int row = idx >> 6;
        int c16 = idx & 63;
        *(uint4*)(sm + row * 1024 + ((c16 ^ (row & 7)) << 4)) =
            *(const uint4*)(qg + (size_t)row * 1024 + (size_t)c16 * 16);
    }

    const int rA0 = r8 + ((jj & 1) << 3);          // A frag rows (m16 tile 0)
    const int rA1 = rA0 + 16;                      // m16 tile 1
    const int cA8 = jj >> 1;
    const int rB0 = wn * 32 + r8 + ((jj >> 1) << 3);   // B keys group 0
    const int rB1 = rB0 + 16;                           // keys group 1
    const int cB8 = jj & 1;
    const int rP  = r8 + ((jj & 1) << 3);
    const int cP8 = jj >> 1;

    float O[2][8][4];
#pragma unroll
    for (int x1 = 0; x1 < 2; x1++)
#pragma unroll
        for (int x2 = 0; x2 < 8; x2++)
#pragma unroll
            for (int x3 = 0; x3 < 4; x3++) { O[x1][x2][x3] = 0.f; }

    int pb = 0;
    stageK(sb + SOFF, 0, 0, 0, tid);
    cpcommit();

    for (int c = 0; c < 16; c++) {
        // ======== QK: 2 key-halves of 256, warp tile m32n32, S over 4 d-quarters ========
        for (int kh = 0; kh < 2; kh++) {
            float S[2][4][4];
#pragma unroll
            for (int mt = 0; mt < 2; mt++)
#pragma unroll
                for (int nt = 0; nt < 4; nt++)
#pragma unroll
                    for (int t = 0; t < 4; t++) { S[mt][nt][t] = 0.f; }

            for (int dq = 0; dq < 4; dq++) {
                cpwait0();
                __syncthreads();
                uint32_t nb = sb + SOFF + ((uint32_t)(pb ^ 1) << 16);
                if (dq < 3)       stageK(nb, c, kh, dq + 1, tid);
                else if (kh == 0) stageK(nb, c, 1, 0, tid);
                else              stageV(nb, c, 0, tid);
                cpcommit();
                uint32_t stg = sb + SOFF + ((uint32_t)pb << 16);

#pragma unroll 4
                for (int ks = 0; ks < 8; ks++) {
                    int cq = dq * 16 + ks * 2 + cA8;   // Q c16 index (0..63)
                    uint32_t a00, a01, a02, a03, a10, a11, a12, a13;
                    ldm4(a00, a01, a02, a03, sb + (uint32_t)(rA0 * 1024 + ((cq ^ (rA0 & 7)) << 4)));
                    ldm4(a10, a11, a12, a13, sb + (uint32_t)(rA1 * 1024 + ((cq ^ (rA1 & 7)) << 4)));
                    int ck = ks * 2 + cB8;             // K-stage c16 index (0..15)
                    uint32_t b0, b1, b2, b3;
                    ldm4(b0, b1, b2, b3, stg + (uint32_t)(rB0 * 256 + ((ck ^ (rB0 & 7)) << 4)));
                    mmab(S[0][0][0], S[0][0][1], S[0][0][2], S[0][0][3], a00, a01, a02, a03, b0, b1);
                    mmab(S[0][1][0], S[0][1][1], S[0][1][2], S[0][1][3], a00, a01, a02, a03, b2, b3);
                    mmab(S[1][0][0], S[1][0][1], S[1][0][2], S[1][0][3], a10, a11, a12, a13, b0, b1);
                    mmab(S[1][1][0], S[1][1][1], S[1][1][2], S[1][1][3], a10, a11, a12, a13, b2, b3);
                    ldm4(b0, b1, b2, b3, stg + (uint32_t)(rB1 * 256 + ((ck ^ (rB1 & 7)) << 4)));
                    mmab(S[0][2][0], S[0][2][1], S[0][2][2], S[0][2][3], a00, a01, a02, a03, b0, b1);
                    mmab(S[0][3][0], S[0][3][1], S[0][3][2], S[0][3][3], a00, a01, a02, a03, b2, b3);
                    mmab(S[1][2][0], S[1][2][1], S[1][2][2], S[1][2][3], a10, a11, a12, a13, b0, b1);
                    mmab(S[1][3][0], S[1][3][1], S[1][3][2], S[1][3][3], a10, a11, a12, a13, b2, b3);
                }
                pb ^= 1;
            }
            // E1 = exp(S*SC) -> smem bf16, partial row sums
#pragma unroll
            for (int mt = 0; mt < 2; mt++) {
                float pr0 = 0.f, pr1 = 0.f;
                int rw0 = mt * 16 + gid;
                int rw1 = rw0 + 8;
#pragma unroll
                for (int nt = 0; nt < 4; nt++) {
                    float e0 = __expf(S[mt][nt][0] * SC), e1 = __expf(S[mt][nt][1] * SC);
                    float e2 = __expf(S[mt][nt][2] * SC), e3 = __expf(S[mt][nt][3] * SC);
                    pr0 += e0 + e1; pr1 += e2 + e3;
                    int key = kh * 256 + wn * 32 + nt * 8 + tig * 2;
                    *(__nv_bfloat162*)(sm + EOFF + rw0 * 1024 + (((key >> 3) ^ (rw0 & 7)) << 4) + ((key & 7) << 1)) = __floats2bfloat162_rn(e0, e1);
                    *(__nv_bfloat162*)(sm + EOFF + rw1 * 1024 + (((key >> 3) ^ (rw1 & 7)) << 4) + ((key & 7) << 1)) = __floats2bfloat162_rn(e2, e3);
                }
                pr0 += __shfl_xor_sync(0xffffffffu, pr0, 1);
                pr0 += __shfl_xor_sync(0xffffffffu, pr0, 2);
                pr1 += __shfl_xor_sync(0xffffffffu, pr1, 1);
                pr1 += __shfl_xor_sync(0xffffffffu, pr1, 2);
                if (tig == 0) {
                    srow[wn * 32 + rw0] += pr0;
                    srow[wn * 32 + rw1] += pr1;
                }
            }
        }
        __syncthreads();

        // ======== chunk softmax -> E2 in place, Z accum, cls ========
        {
            int row = tid >> 3;
            int seg = tid & 7;
            float s = 0.f;
#pragma unroll
            for (int g = 0; g < 8; g++) { s += srow[g * 32 + row]; }
            float rinv = 1.f / s;
            float z = 0.f;
#pragma unroll
            for (int i = 0; i < 8; i++) {
                int c16 = seg * 8 + i;
                uint32_t* p = (uint32_t*)(sm + EOFF + row * 1024 + ((c16 ^ (row & 7)) << 4));
#pragma unroll
                for (int qq = 0; qq < 4; qq++) {
                    float2 fv = __bfloat1622float2(*(__nv_bfloat162*)(p + qq));
                    float u0 = __expf(fv.x * rinv);
                    float u1 = __expf(fv.y * rinv);
                    z += u0 + u1;
                    *(__nv_bfloat162*)(p + qq) = __floats2bfloat162_rn(u0, u1);
                    if (blockIdx.x == 0 && row == 0) {
                        int col = c16 * 8 + qq * 2;
                        g_cls[c * 512 + col]     = u0;
                        g_cls[c * 512 + col + 1] = u1;
                    }
                }
            }
            z += __shfl_xor_sync(0xffffffffu, z, 1);
            z += __shfl_xor_sync(0xffffffffu, z, 2);
            z += __shfl_xor_sync(0xffffffffu, z, 4);
            if (seg == 0) Zb[row] += z;
        }

        // ======== PV: 8 stages of 64 keys x full d, warp m32n64 ========
        for (int kv = 0; kv < 8; kv++) {
            cpwait0();
            __syncthreads();
            if (kv == 0) srow[tid] = 0.f;
            uint32_t nb = sb + SOFF + ((uint32_t)(pb ^ 1) << 16);
            if (kv < 7)      { stageV(nb, c, kv + 1, tid); }
            else if (c < 15) { stageK(nb, c + 1, 0, 0, tid); }
            cpcommit();
            uint32_t stg = sb + SOFF + ((uint32_t)pb << 16);
#pragma unroll
            for (int ks = 0; ks < 4; ks++) {
                uint32_t a00, a01, a02, a03, a10, a11, a12, a13;
                int ce  = kv * 8 + ks * 2 + cP8;
                int ra1 = 16 + rP;
                ldm4(a00, a01, a02, a03, sb + (uint32_t)(EOFF + rP  * 1024 + ((ce ^ (rP  & 7)) << 4)));
                ldm4(a10, a11, a12, a13, sb + (uint32_t)(EOFF + ra1 * 1024 + ((ce ^ (ra1 & 7)) << 4)));
                int rv = ks * 16 + rP;
#pragma unroll
                for (int nt = 0; nt < 4; nt++) {
                    uint32_t b0, b1, b2, b3;
                    int cv = wd * 8 + nt * 2 + cP8;
                    ldm4t(b0, b1, b2, b3, stg + (uint32_t)(rv * 1024 + ((cv ^ (rv & 7)) << 4)));
                    mmab(O[0][2*nt  ][0], O[0][2*nt  ][1], O[0][2*nt  ][2], O[0][2*nt  ][3], a00, a01, a02, a03, b0, b1);
                    mmab(O[0][2*nt+1][0], O[0][2*nt+1][1], O[0][2*nt+1][2], O[0][2*nt+1][3], a00, a01, a02, a03, b2, b3);
                    mmab(O[1][2*nt  ][0], O[1][2*nt  ][1], O[1][2*nt  ][2], O[1][2*nt  ][3], a10, a11, a12, a13, b0, b1);
                    mmab(O[1][2*nt+1][0], O[1][2*nt+1][1], O[1][2*nt+1][2], O[1][2*nt+1][3], a10, a11, a12, a13, b2, b3);
                }
            }
            pb ^= 1;
        }
    }
    __syncthreads();

    // normalize + store bf16
#pragma unroll
    for (int mt = 0; mt < 2; mt++) {
        int r0 = mt * 16 + gid;
        float z0 = 1.f / Zb[r0];
        float z1 = 1.f / Zb[r0 + 8];
#pragma unroll
        for (int nt = 0; nt < 8; nt++) {
            int col = wd * 64 + nt * 8 + tig * 2;
            *(__nv_bfloat162*)&g_ab[(size_t)(q0 + r0) * DMOD + col]     = __floats2bfloat162_rn(O[mt][nt][0] * z0, O[mt][nt][1] * z0);
            *(__nv_bfloat162*)&g_ab[(size_t)(q0 + r0 + 8) * DMOD + col] = __floats2bfloat162_rn(O[mt][nt][2] * z1, O[mt][nt][3] * z1);
        }
    }
    if (blockIdx.x == 0 && tid == 0) g_Z0 = Zb[0];
}

// ---------------- bf16 tensor-core QKV projection GEMM ----------------
__global__ __launch_bounds__(256)
void gemm_qkv(const __nv_bfloat16* __restrict__ A,
              const __nv_bfloat16* __restrict__ Wa, const __nv_bfloat16* __restrict__ Wb2, const __nv_bfloat16* __restrict__ Wc,
              const float* __restrict__ ba, const float* __restrict__ bb2, const float* __restrict__ bc,
              __nv_bfloat16* __restrict__ oa, __nv_bfloat16* __restrict__ ob, __nv_bfloat16* __restrict__ oc)
{
    extern __shared__ char smg[];
    uint32_t sb = (uint32_t)__cvta_generic_to_shared(smg);

    const __nv_bfloat16* W;
    const float* bias;
    __nv_bfloat16* out;
    if (blockIdx.z == 0)      { W = Wa;  bias = ba;  out = oa; }
    else if (blockIdx.z == 1) { W = Wb2; bias = bb2; out = ob; }
    else                      { W = Wc;  bias = bc;  out = oc; }

    const int tid  = threadIdx.x;
    const int wd   = tid >> 5;
    const int lane = tid & 31;
    const int r8   = lane & 7;
    const int jj   = lane >> 3;
    const int gid  = lane >> 2;
    const int tig  = lane & 3;
    const int wm   = wd >> 2;
    const int wn   = wd & 3;
    const int bm   = blockIdx.x * 128;
    const int bn   = blockIdx.y * 128;
    const int rP   = r8 + ((jj & 1) << 3);
    const int cP8  = jj >> 1;

    float acc[4][4][4];
#pragma unroll
    for (int mt = 0; mt < 4; mt++)
#pragma unroll
        for (int nt = 0; nt < 4; nt++)
#pragma unroll
            for (int q2 = 0; q2 < 4; q2++) { acc[mt][nt][q2] = 0.f; }

#pragma unroll
    for (int i = 0; i < 4; i++) {
        int idx = i * 256 + tid;
        int row = idx >> 3;
        int c16 = idx & 7;
        cpa16(sb + (uint32_t)(row * 128 + ((c16 ^ (row & 7)) << 4)),
              (const char*)(A + (size_t)(bm + row) * DMOD) + (size_t)c16 * 16);
    }
#pragma unroll
    for (int i = 0; i < 4; i++) {
        int idx = i * 256 + tid;
        int k = idx >> 4;
        int c16 = idx & 15;
        cpa16(sb + (uint32_t)(32768 + k * 256 + ((c16 ^ (k & 7)) << 4)),
              (const char*)(W + (size_t)k * DMOD + bn) + (size_t)c16 * 16);
    }
    cpcommit();

    for (int s = 0; s < 8; s++) {
        cpwait0();
        __syncthreads();
        if (s < 7) {
            int ns = s + 1;
            uint32_t ab = sb + (uint32_t)((ns & 1) * 16384);
            uint32_t wb = sb + (uint32_t)(32768 + (ns & 1) * 16384);
#pragma unroll
            for (int i = 0; i < 4; i++) {
                int idx = i * 256 + tid;
                int row = idx >> 3;
                int c16 = idx & 7;
                cpa16(ab + (uint32_t)(row * 128 + ((c16 ^ (row & 7)) << 4)),
                      (const char*)(A + (size_t)(bm + row) * DMOD + (size_t)ns * 64) + (size_t)c16 * 16);
            }
#pragma unroll
            for (int i = 0; i < 4; i++) {
                int idx = i * 256 + tid;
                int k = idx >> 4;
                int c16 = idx & 15;
                cpa16(wb + (uint32_t)(k * 256 + ((c16 ^ (k & 7)) << 4)),
                      (const char*)(W + (size_t)(ns * 64 + k) * DMOD + bn) + (size_t)c16 * 16);
            }
            cpcommit();
        }
        uint32_t sa = sb + (uint32_t)((s & 1) * 16384);
        uint32_t sw = sb + (uint32_t)(32768 + (s & 1) * 16384);
#pragma unroll
        for (int ks = 0; ks < 4; ks++) {
            uint32_t am[4][4];
            int ck = ks * 2 + cP8;
#pragma unroll
            for (int mt = 0; mt < 4; mt++) {
                int rowA = wm * 64 + mt * 16 + rP;
                ldm4(am[mt][0], am[mt][1], am[mt][2], am[mt][3], sa + (uint32_t)(rowA * 128 + ((ck ^ (rowA & 7)) << 4)));
            }
#pragma unroll
            for (int nt2 = 0; nt2 < 2; nt2++) {
                uint32_t b0, b1, b2, b3;
                int rv = ks * 16 + rP;
                int cv = wn * 4 + nt2 * 2 + cP8;
                ldm4t(b0, b1, b2, b3, sw + (uint32_t)(rv * 256 + ((cv ^ (rv & 7)) << 4)));
#pragma unroll
                for (int mt = 0; mt < 4; mt++) {
                    mmab(acc[mt][2*nt2  ][0], acc[mt][2*nt2  ][1], acc[mt][2*nt2  ][2], acc[mt][2*nt2  ][3], am[mt][0], am[mt][1], am[mt][2], am[mt][3], b0, b1);
                    mmab(acc[mt][2*nt2+1][0], acc[mt][2*nt2+1][1], acc[mt][2*nt2+1][2], acc[mt][2*nt2+1][3], am[mt][0], am[mt][1], am[mt][2], am[mt][3], b2, b3);
                }
            }
        }
    }

#pragma unroll
    for (int mt = 0; mt < 4; mt++) {
        int row0 = bm + wm * 64 + mt * 16 + gid;
        int row1 = row0 + 8;
#pragma unroll
        for (int nt = 0; nt < 4; nt++) {
            int col = bn + wn * 32 + nt * 8 + tig * 2;
            float bx = bias[col];
            float by = bias[col + 1];
            *(__nv_bfloat162*)&out[(size_t)row0 * DMOD + col] = __floats2bfloat162_rn(acc[mt][nt][0] + bx, acc[mt][nt][1] + by);
            *(__nv_bfloat162*)&out[(size_t)row1 * DMOD + col] = __floats2bfloat162_rn(acc[mt][nt][2] + bx, acc[mt][nt][3] + by);
        }
    }
}

// ------------- bf16 output projection GEMM: out = A@W + bias + resid (fp32) -------------
__global__ __launch_bounds__(256)
void gemm_out(const __nv_bfloat16* __restrict__ A, const __nv_bfloat16* __restrict__ W,
              const float* __restrict__ bias, const float* __restrict__ resid,
              float* __restrict__ out)
{
    extern __shared__ char smg[];
    uint32_t sb = (uint32_t)__cvta_generic_to_shared(smg);

    const int tid  = threadIdx.x;
    const int wd   = tid >> 5;
    const int lane = tid & 31;
    const int r8   = lane & 7;
    const int jj   = lane >> 3;
    const int gid  = lane >> 2;
    const int tig  = lane & 3;
    const int wm   = wd >> 2;
    const int wn   = wd & 3;
    const int bm   = blockIdx.x * 128;
    const int bn   = blockIdx.y * 128;
    const int rP   = r8 + ((jj & 1) << 3);
    const int cP8  = jj >> 1;

    float acc[4][4][4];
#pragma unroll
    for (int mt = 0; mt < 4; mt++)
#pragma unroll
        for (int nt = 0; nt < 4; nt++)
#pragma unroll
            for (int q2 = 0; q2 < 4; q2++) { acc[mt][nt][q2] = 0.f; }

#pragma unroll
    for (int i = 0; i < 4; i++) {
        int idx = i * 256 + tid;
        int row = idx >> 3;
        int c16 = idx & 7;
        cpa16(sb + (uint32_t)(row * 128 + ((c16 ^ (row & 7)) << 4)),
              (const char*)(A + (size_t)(bm + row) * DMOD) + (size_t)c16 * 16);
    }
#pragma unroll
    for (int i = 0; i < 4; i++) {
        int idx = i * 256 + tid;
        int k = idx >> 4;
        int c16 = idx & 15;
        cpa16(sb + (uint32_t)(32768 + k * 256 + ((c16 ^ (k & 7)) << 4)),
              (const char*)(W + (size_t)k * DMOD + bn) + (size_t)c16 * 16);
    }
    cpcommit();

    for (int s = 0; s < 8; s++) {
        cpwait0();
        __syncthreads();
        if (s < 7) {
            int ns = s + 1;
            uint32_t ab = sb + (uint32_t)((ns & 1) * 16384);
            uint32_t wb = sb + (uint32_t)(32768 + (ns & 1) * 16384);
#pragma unroll
            for (int i = 0; i < 4; i++) {
                int idx = i * 256 + tid;
                int row = idx >> 3;
                int c16 = idx & 7;
                cpa16(ab + (uint32_t)(row * 128 + ((c16 ^ (row & 7)) << 4)),
                      (const char*)(A + (size_t)(bm + row) * DMOD + (size_t)ns * 64) + (size_t)c16 * 16);
            }
#pragma unroll
            for (int i = 0; i < 4; i++) {
                int idx = i * 256 + tid;
                int k = idx >> 4;
                int c16 = idx & 15;
                cpa16(wb + (uint32_t)(k * 256 + ((c16 ^ (k & 7)) << 4)),
                      (const char*)(W + (size_t)(ns * 64 + k) * DMOD + bn) + (size_t)c16 * 16);
            }
            cpcommit();
        }
        uint32_t sa = sb + (uint32_t)((s & 1) * 16384);
        uint32_t sw = sb + (uint32_t)(32768 + (s & 1) * 16384);
#pragma unroll
        for (int ks = 0; ks < 4; ks++) {
            uint32_t am[4][4];
            int ck = ks * 2 + cP8;
#pragma unroll
            for (int mt = 0; mt < 4; mt++) {
                int rowA = wm * 64 + mt * 16 + rP;
                ldm4(am[mt][0], am[mt][1], am[mt][2], am[mt][3], sa + (uint32_t)(rowA * 128 + ((ck ^ (rowA & 7)) << 4)));
            }
#pragma unroll
            for (int nt2 = 0; nt2 < 2; nt2++) {
                uint32_t b0, b1, b2, b3;
                int rv = ks * 16 + rP;
                int cv = wn * 4 + nt2 * 2 + cP8;
                ldm4t(b0, b1, b2, b3, sw + (uint32_t)(rv * 256 + ((cv ^ (rv & 7)) << 4)));
#pragma unroll
                for (int mt = 0; mt < 4; mt++) {
                    mmab(acc[mt][2*nt2  ][0], acc[mt][2*nt2  ][1], acc[mt][2*nt2  ][2], acc[mt][2*nt2  ][3], am[mt][0], am[mt][1], am[mt][2], am[mt][3], b0, b1);
                    mmab(acc[mt][2*nt2+1][0], acc[mt][2*nt2+1][1], acc[mt][2*nt2+1][2], acc[mt][2*nt2+1][3], am[mt][0], am[mt][1], am[mt][2], am[mt][3], b2, b3);
                }
            }
        }
    }

#pragma unroll
    for (int mt = 0; mt < 4; mt++) {
        int row0 = bm + wm * 64 + mt * 16 + gid;
        int row1 = row0 + 8;
#pragma unroll
        for (int nt = 0; nt < 4; nt++) {
            int col = bn + wn * 32 + nt * 8 + tig * 2;
            float bx = bias[col];
            float by = bias[col + 1];
            float2 ra = *(const float2*)&resid[(size_t)row0 * DMOD + col];
            float2 rb = *(const float2*)&resid[(size_t)row1 * DMOD + col];
            float2 v0 = make_float2(acc[mt][nt][0] + bx + ra.x, acc[mt][nt][1] + by + ra.y);
            float2 v1 = make_float2(acc[mt][nt][2] + bx + rb.x, acc[mt][nt][3] + by + rb.y);
            *(float2*)&out[(size_t)row0 * DMOD + col] = v0;
            *(float2*)&out[(size_t)row1 * DMOD + col] = v1;
        }
    }
}

__global__ void convf2b(const float* __restrict__ s, __nv_bfloat16* __restrict__ d, int n4)
{
    int i = blockIdx.x * blockDim.x + threadIdx.x;
    if (i < n4) {
        float4 v = ((const float4*)s)[i];
        ((__nv_bfloat162*)d)[2 * i]     = __floats2bfloat162_rn(v.x, v.y);
        ((__nv_bfloat162*)d)[2 * i + 1] = __floats2bfloat162_rn(v.z, v.w);
    }
}

// all 4 weight conversions in one launch
__global__ void convw4(const float* __restrict__ Wq, const float* __restrict__ Wk,
                       const float* __restrict__ Wv, const float* __restrict__ Wo)
{
    int i = blockIdx.x * blockDim.x + threadIdx.x;   // 0 .. 4*65536-1
    int w = i >> 16;
    int j = i & 65535;
    const float* s;
    __nv_bfloat16* d;
    if (w == 0)      { s = Wq; d = g_w0; }
    else if (w == 1) { s = Wk; d = g_w1; }
    else if (w == 2) { s = Wv; d = g_w2; }
    else             { s = Wo; d = g_w3; }
    float4 v = ((const float4*)s)[j];
    ((__nv_bfloat162*)d)[2 * j]     = __floats2bfloat162_rn(v.x, v.y);
    ((__nv_bfloat162*)d)[2 * j + 1] = __floats2bfloat162_rn(v.z, v.w);
}

__global__ void cls_kernel(float* __restrict__ out)
{
    int m = blockIdx.x * 256 + threadIdx.x;
    out[m] = g_cls[m] / g_Z0;
}

extern "C" void kernel_launch(void* const* d_in, const int* in_sizes, int n_in,
                              void* d_out, int out_size)
{
    const float* x  = (const float*)d_in[0];
    const float* Wq = (const float*)d_in[1];
    const float* bq = (const float*)d_in[2];
    const float* Wk = (const float*)d_in[3];
    const float* bk = (const float*)d_in[4];
    const float* Wv = (const float*)d_in[5];
    const float* bv = (const float*)d_in[6];
    const float* Wo = (const float*)d_in[7];
    const float* bo = (const float*)d_in[8];
    float* out = (float*)d_out;

    __nv_bfloat16 *xb = 0, *w0 = 0, *w1 = 0, *w2 = 0, *w3 = 0, *qb = 0, *kb = 0, *vb = 0, *ab = 0;
    cudaGetSymbolAddress((void**)&xb, g_xb);
    cudaGetSymbolAddress((void**)&w0, g_w0);
    cudaGetSymbolAddress((void**)&w1, g_w1);
    cudaGetSymbolAddress((void**)&w2, g_w2);
    cudaGetSymbolAddress((void**)&w3, g_w3);
    cudaGetSymbolAddress((void**)&qb, g_qb);
    cudaGetSymbolAddress((void**)&kb, g_kb);
    cudaGetSymbolAddress((void**)&vb, g_vb);
    cudaGetSymbolAddress((void**)&ab, g_ab);

    cudaFuncSetAttribute(attn2, cudaFuncAttributeMaxDynamicSharedMemorySize, SM_TOTAL);
    cudaFuncSetAttribute(gemm_qkv, cudaFuncAttributeMaxDynamicSharedMemorySize, 65536);
    cudaFuncSetAttribute(gemm_out, cudaFuncAttributeMaxDynamicSharedMemorySize, 65536);

    convf2b<<<4096, 256>>>(x, xb, NTOK * DMOD / 4);
    convw4<<<1024, 256>>>(Wq, Wk, Wv, Wo);

    dim3 gq(64, 4, 3);
    gemm_qkv<<<gq, 256, 65536>>>(xb, w0, w1, w2, bq, bk, bv, qb, kb, vb);

    attn2<<<256, 256, SM_TOTAL>>>();

    dim3 gg(64, 4);
    gemm_out<<<gg, 256, 65536>>>(ab, w3, bo, x, out);
    cls_kernel<<<32, 256>>>(out + (size_t)NTOK * DMOD);
}

// round 12
// speedup vs baseline: 9.1132x; 1.0423x over previous
#include <cuda_runtime.h>
#include <cuda_bf16.h>
#include <cstdint>

constexpr int NTOK = 8192;
constexpr int DMOD = 512;

__device__ __nv_bfloat16 g_xb[NTOK * DMOD];
__device__ __nv_bfloat16 g_w0[DMOD * DMOD];
__device__ __nv_bfloat16 g_w1[DMOD * DMOD];
__device__ __nv_bfloat16 g_w2[DMOD * DMOD];
__device__ __nv_bfloat16 g_w3[DMOD * DMOD];
__device__ __nv_bfloat16 g_qb[NTOK * DMOD];
__device__ __nv_bfloat16 g_kb[NTOK * DMOD];
__device__ __nv_bfloat16 g_vb[NTOK * DMOD];
__device__ __nv_bfloat16 g_ab[NTOK * DMOD];
__device__ float g_cls[NTOK];
__device__ float g_Z0;

// attn2 smem: Q[0,32K) E[32K,64K) KV 2x64K [64K,192K) srow[196608,+2K) Zb[198656,+128)
constexpr int EOFF = 32768;
constexpr int SOFF = 65536;
constexpr int ROFF = 196608;
constexpr int ZOFF = 198656;
constexpr int SM_TOTAL = 198784;

__device__ __forceinline__ void ldm4(uint32_t &r0, uint32_t &r1, uint32_t &r2, uint32_t &r3, uint32_t ad)
{
    asm volatile("ldmatrix.sync.aligned.m8n8.x4.shared.b16 {%0,%1,%2,%3},[%4];"
                 : "=r"(r0), "=r"(r1), "=r"(r2), "=r"(r3) : "r"(ad));
}
__device__ __forceinline__ void ldm4t(uint32_t &r0, uint32_t &r1, uint32_t &r2, uint32_t &r3, uint32_t ad)
{
    asm volatile("ldmatrix.sync.aligned.m8n8.x4.trans.shared.b16 {%0,%1,%2,%3},[%4];"
                 : "=r"(r0), "=r"(r1), "=r"(r2), "=r"(r3) : "r"(ad));
}
__device__ __forceinline__ void mmab(float &c0, float &c1, float &c2, float &c3,
                                     uint32_t a0, uint32_t a1, uint32_t a2, uint32_t a3,
                                     uint32_t b0, uint32_t b1)
{
    asm volatile("mma.sync.aligned.m16n8k16.row.col.f32.bf16.bf16.f32 "
                 "{%0,%1,%2,%3},{%4,%5,%6,%7},{%8,%9},{%0,%1,%2,%3};"
                 : "+f"(c0), "+f"(c1), "+f"(c2), "+f"(c3)
                 : "r"(a0), "r"(a1), "r"(a2), "r"(a3), "r"(b0), "r"(b1));
}
__device__ __forceinline__ void cpa16(uint32_t s, const void* g)
{
    asm volatile("cp.async.cg.shared.global [%0],[%1],16;" :: "r"(s), "l"(g));
}
__device__ __forceinline__ void cpcommit() { asm volatile("cp.async.commit_group;"); }
__device__ __forceinline__ void cpwait0()  { asm volatile("cp.async.wait_group 0;"); }

// K stage: 512 keys x 64 d-eighth (64KB), rows 128B, swizzled; 512 threads
__device__ __forceinline__ void stageK(uint32_t buf, int c, int dq, int tid)
{
#pragma unroll
    for (int i = 0; i < 8; i++) {
        int idx = i * 512 + tid;
        int row = idx >> 3;
        int c16 = idx & 7;
        cpa16(buf + (uint32_t)(row * 128 + ((c16 ^ (row & 7)) << 4)),
              (const char*)(g_kb + (size_t)(c * 512 + row) * DMOD) + dq * 128 + c16 * 16);
    }
}
// V stage: 64 keys x 512 d (64KB), rows 1024B, swizzled; 512 threads
__device__ __forceinline__ void stageV(uint32_t buf, int c, int kv, int tid)
{
#pragma unroll
    for (int i = 0; i < 8; i++) {
        int idx = i * 512 + tid;
        int row = idx >> 6;
        int c16 = idx & 63;
        cpa16(buf + (uint32_t)(row * 1024 + ((c16 ^ (row & 7)) << 4)),
              (const char*)(g_vb + (size_t)(c * 512 + kv * 64 + row) * DMOD) + c16 * 16);
    }
}

__global__ __launch_bounds__(512)
void attn2()
{
    extern __shared__ char sm[];
    uint32_t sb = (uint32_t)__cvta_generic_to_shared(sm);
    float* srow = (float*)(sm + ROFF);
    float* Zb   = (float*)(sm + ZOFF);

    const int tid  = threadIdx.x;
    const int wd   = tid >> 5;     // 0..15
    const int lane = tid & 31;
    const int r8   = lane & 7;
    const int jj   = lane >> 3;
    const int gid  = lane >> 2;
    const int tig  = lane & 3;
    const int wn   = wd;           // QK: 32-key group of 512; PV: 32-col group of 512
    const int q0   = blockIdx.x << 5;
    const float SC = 0.044194173824159216f;  // 1/sqrt(512)

    if (tid < 32) Zb[tid] = 0.f;
    srow[tid] = 0.f;

    // Q tile (32x512 bf16) -> smem swizzled, rows 1024B
    const char* qg = (const char*)(g_qb + (size_t)q0 * DMOD);
#pragma unroll
    for (int i = 0; i < 4; i++) {
        int idx = i * 512 + tid;
        int row = idx >> 6;
        int c16 = idx & 63;
        *(uint4*)(sm + row * 1024 + ((c16 ^ (row & 7)) << 4)) =
            *(const uint4*)(qg + (size_t)row * 1024 + (size_t)c16 * 16);
    }

    const int rA0 = r8 + ((jj & 1) << 3);            // A frag rows, m16 tile 0
    const int rA1 = rA0 + 16;                        // m16 tile 1
    const int cA8 = jj >> 1;
    const int rB0 = wn * 32 + r8 + ((jj >> 1) << 3); // K keys group 0
    const int rB1 = rB0 + 16;                        // keys group 1
    const int cB8 = jj & 1;
    const int rP  = r8 + ((jj & 1) << 3);
    const int cP8 = jj >> 1;

    float O[2][4][4];
#pragma unroll
    for (int x1 = 0; x1 < 2; x1++)
#pragma unroll
        for (int x2 = 0; x2 < 4; x2++)
#pragma unroll
            for (int x3 = 0; x3 < 4; x3++) { O[x1][x2][x3] = 0.f; }

    int pb = 0;
    stageK(sb + SOFF, 0, 0, tid);
    cpcommit();

    for (int c = 0; c < 16; c++) {
        // ======== QK: warp m32n32 over full 512-key chunk, 8 d-eighth stages ========
        float S[2][4][4];
#pragma unroll
        for (int mt = 0; mt < 2; mt++)
#pragma unroll
            for (int nt = 0; nt < 4; nt++)
#pragma unroll
                for (int t = 0; t < 4; t++) { S[mt][nt][t] = 0.f; }

        for (int dq = 0; dq < 8; dq++) {
            cpwait0();
            __syncthreads();
            uint32_t nb = sb + SOFF + ((uint32_t)(pb ^ 1) << 16);
            if (dq < 7) stageK(nb, c, dq + 1, tid);
            else        stageV(nb, c, 0, tid);
            cpcommit();
            uint32_t stg = sb + SOFF + ((uint32_t)pb << 16);

#pragma unroll
            for (int ks = 0; ks < 4; ks++) {
                int cq = dq * 8 + ks * 2 + cA8;     // Q c16 index 0..63
                uint32_t a00, a01, a02, a03, a10, a11, a12, a13;
                ldm4(a00, a01, a02, a03, sb + (uint32_t)(rA0 * 1024 + ((cq ^ (rA0 & 7)) << 4)));
                ldm4(a10, a11, a12, a13, sb + (uint32_t)(rA1 * 1024 + ((cq ^ (rA1 & 7)) << 4)));
                int ck = ks * 2 + cB8;              // K-stage c16 index 0..7
                uint32_t b0, b1, b2, b3;
                ldm4(b0, b1, b2, b3, stg + (uint32_t)(rB0 * 128 + ((ck ^ (rB0 & 7)) << 4)));
                mmab(S[0][0][0], S[0][0][1], S[0][0][2], S[0][0][3], a00, a01, a02, a03, b0, b1);
                mmab(S[0][1][0], S[0][1][1], S[0][1][2], S[0][1][3], a00, a01, a02, a03, b2, b3);
                mmab(S[1][0][0], S[1][0][1], S[1][0][2], S[1][0][3], a10, a11, a12, a13, b0, b1);
                mmab(S[1][1][0], S[1][1][1], S[1][1][2], S[1][1][3], a10, a11, a12, a13, b2, b3);
                ldm4(b0, b1, b2, b3, stg + (uint32_t)(rB1 * 128 + ((ck ^ (rB1 & 7)) << 4)));
                mmab(S[0][2][0], S[0][2][1], S[0][2][2], S[0][2][3], a00, a01, a02, a03, b0, b1);
                mmab(S[0][3][0], S[0][3][1], S[0][3][2], S[0][3][3], a00, a01, a02, a03, b2, b3);
                mmab(S[1][2][0], S[1][2][1], S[1][2][2], S[1][2][3], a10, a11, a12, a13, b0, b1);
                mmab(S[1][3][0], S[1][3][1], S[1][3][2], S[1][3][3], a10, a11, a12, a13, b2, b3);
            }
            pb ^= 1;
        }
        // E1 = exp(S*SC) -> smem bf16, partial row sums
#pragma unroll
        for (int mt = 0; mt < 2; mt++) {
            float pr0 = 0.f, pr1 = 0.f;
            int rw0 = mt * 16 + gid;
            int rw1 = rw0 + 8;
#pragma unroll
            for (int nt = 0; nt < 4; nt++) {
                float e0 = __expf(S[mt][nt][0] * SC), e1 = __expf(S[mt][nt][1] * SC);
                float e2 = __expf(S[mt][nt][2] * SC), e3 = __expf(S[mt][nt][3] * SC);
                pr0 += e0 + e1; pr1 += e2 + e3;
                int key = wn * 32 + nt * 8 + tig * 2;
                *(__nv_bfloat162*)(sm + EOFF + rw0 * 1024 + (((key >> 3) ^ (rw0 & 7)) << 4) + ((key & 7) << 1)) = __floats2bfloat162_rn(e0, e1);
                *(__nv_bfloat162*)(sm + EOFF + rw1 * 1024 + (((key >> 3) ^ (rw1 & 7)) << 4) + ((key & 7) << 1)) = __floats2bfloat162_rn(e2, e3);
            }
            pr0 += __shfl_xor_sync(0xffffffffu, pr0, 1);
            pr0 += __shfl_xor_sync(0xffffffffu, pr0, 2);
            pr1 += __shfl_xor_sync(0xffffffffu, pr1, 1);
            pr1 += __shfl_xor_sync(0xffffffffu, pr1, 2);
            if (tig == 0) {
                srow[wn * 32 + rw0] += pr0;
                srow[wn * 32 + rw1] += pr1;
            }
        }
        __syncthreads();

        // ======== chunk softmax -> E2 in place, Z accum, cls ========
        {
            int row = tid >> 4;
            int seg = tid & 15;
            float s = 0.f;
#pragma unroll
            for (int g = 0; g < 16; g++) { s += srow[g * 32 + row]; }
            float rinv = 1.f / s;
            float z = 0.f;
#pragma unroll
            for (int i = 0; i < 4; i++) {
                int c16 = seg * 4 + i;
                uint32_t* p = (uint32_t*)(sm + EOFF + row * 1024 + ((c16 ^ (row & 7)) << 4));
#pragma unroll
                for (int qq = 0; qq < 4; qq++) {
                    float2 fv = __bfloat1622float2(*(__nv_bfloat162*)(p + qq));
                    float u0 = __expf(fv.x * rinv);
                    float u1 = __expf(fv.y * rinv);
                    z += u0 + u1;
                    *(__nv_bfloat162*)(p + qq) = __floats2bfloat162_rn(u0, u1);
                    if (blockIdx.x == 0 && row == 0) {
                        int col = c16 * 8 + qq * 2;
                        g_cls[c * 512 + col]     = u0;
                        g_cls[c * 512 + col + 1] = u1;
                    }
                }
            }
            z += __shfl_xor_sync(0xffffffffu, z, 1);
            z += __shfl_xor_sync(0xffffffffu, z, 2);
            z += __shfl_xor_sync(0xffffffffu, z, 4);
            z += __shfl_xor_sync(0xffffffffu, z, 8);
            if (seg == 0) Zb[row] += z;
        }

        // ======== PV: 8 stages of 64 keys x full d, warp m32n32 ========
        for (int kv = 0; kv < 8; kv++) {
            cpwait0();
            __syncthreads();
            if (kv == 0) srow[tid] = 0.f;
            uint32_t nb = sb + SOFF + ((uint32_t)(pb ^ 1) << 16);
            if (kv < 7)      { stageV(nb, c, kv + 1, tid); }
            else if (c < 15) { stageK(nb, c + 1, 0, tid); }
            cpcommit();
            uint32_t stg = sb + SOFF + ((uint32_t)pb << 16);
#pragma unroll
            for (int ks = 0; ks < 4; ks++) {
                uint32_t a00, a01, a02, a03, a10, a11, a12, a13;
                int ce  = kv * 8 + ks * 2 + cP8;
                int ra1 = 16 + rP;
                ldm4(a00, a01, a02, a03, sb + (uint32_t)(EOFF + rP  * 1024 + ((ce ^ (rP  & 7)) << 4)));
                ldm4(a10, a11, a12, a13, sb + (uint32_t)(EOFF + ra1 * 1024 + ((ce ^ (ra1 & 7)) << 4)));
                int rv = ks * 16 + rP;
#pragma unroll
                for (int nt2 = 0; nt2 < 2; nt2++) {
                    uint32_t b0, b1, b2, b3;
                    int cv = wn * 4 + nt2 * 2 + cP8;
                    ldm4t(b0, b1, b2, b3, stg + (uint32_t)(rv * 1024 + ((cv ^ (rv & 7)) << 4)));
                    mmab(O[0][2*nt2  ][0], O[0][2*nt2  ][1], O[0][2*nt2  ][2], O[0][2*nt2  ][3], a00, a01, a02, a03, b0, b1);
                    mmab(O[0][2*nt2+1][0], O[0][2*nt2+1][1], O[0][2*nt2+1][2], O[0][2*nt2+1][3], a00, a01, a02, a03, b2, b3);
                    mmab(O[1][2*nt2  ][0], O[1][2*nt2  ][1], O[1][2*nt2  ][2], O[1][2*nt2  ][3], a10, a11, a12, a13, b0, b1);
                    mmab(O[1][2*nt2+1][0], O[1][2*nt2+1][1], O[1][2*nt2+1][2], O[1][2*nt2+1][3], a10, a11, a12, a13, b2, b3);
                }
            }
            pb ^= 1;
        }
    }
    __syncthreads();

    // normalize + store bf16
#pragma unroll
    for (int mt = 0; mt < 2; mt++) {
        int r0 = mt * 16 + gid;
        float z0 = 1.f / Zb[r0];
        float z1 = 1.f / Zb[r0 + 8];
#pragma unroll
        for (int nt = 0; nt < 4; nt++) {
            int col = wn * 32 + nt * 8 + tig * 2;
            *(__nv_bfloat162*)&g_ab[(size_t)(q0 + r0) * DMOD + col]     = __floats2bfloat162_rn(O[mt][nt][0] * z0, O[mt][nt][1] * z0);
            *(__nv_bfloat162*)&g_ab[(size_t)(q0 + r0 + 8) * DMOD + col] = __floats2bfloat162_rn(O[mt][nt][2] * z1, O[mt][nt][3] * z1);
        }
    }
    if (blockIdx.x == 0 && tid == 0) g_Z0 = Zb[0];
}

// ---------------- bf16 tensor-core QKV projection GEMM ----------------
__global__ __launch_bounds__(256)
void gemm_qkv(const __nv_bfloat16* __restrict__ A,
              const __nv_bfloat16* __restrict__ Wa, const __nv_bfloat16* __restrict__ Wb2, const __nv_bfloat16* __restrict__ Wc,
              const float* __restrict__ ba, const float* __restrict__ bb2, const float* __restrict__ bc,
              __nv_bfloat16* __restrict__ oa, __nv_bfloat16* __restrict__ ob, __nv_bfloat16* __restrict__ oc)
{
    extern __shared__ char smg[];
    uint32_t sb = (uint32_t)__cvta_generic_to_shared(smg);

    const __nv_bfloat16* W;
    const float* bias;
    __nv_bfloat16* out;
    if (blockIdx.z == 0)      { W = Wa;  bias = ba;  out = oa; }
    else if (blockIdx.z == 1) { W = Wb2; bias = bb2; out = ob; }
    else                      { W = Wc;  bias = bc;  out = oc; }

    const int tid  = threadIdx.x;
    const int wd   = tid >> 5;
    const int lane = tid & 31;
    const int r8   = lane & 7;
    const int jj   = lane >> 3;
    const int gid  = lane >> 2;
    const int tig  = lane & 3;
    const int wm   = wd >> 2;
    const int wn   = wd & 3;
    const int bm   = blockIdx.x * 128;
    const int bn   = blockIdx.y * 128;
    const int rP   = r8 + ((jj & 1) << 3);
    const int cP8  = jj >> 1;

    float acc[4][4][4];
#pragma unroll
    for (int mt = 0; mt < 4; mt++)
#pragma unroll
        for (int nt = 0; nt < 4; nt++)
#pragma unroll
            for (int q2 = 0; q2 < 4; q2++) { acc[mt][nt][q2] = 0.f; }

#pragma unroll
    for (int i = 0; i < 4; i++) {
        int idx = i * 256 + tid;
        int row = idx >> 3;
        int c16 = idx & 7;
        cpa16(sb + (uint32_t)(row * 128 + ((c16 ^ (row & 7)) << 4)),
              (const char*)(A + (size_t)(bm + row) * DMOD) + (size_t)c16 * 16);
    }
#pragma unroll
    for (int i = 0; i < 4; i++) {
        int idx = i * 256 + tid;
        int k = idx >> 4;
        int c16 = idx & 15;
        cpa16(sb + (uint32_t)(32768 + k * 256 + ((c16 ^ (k & 7)) << 4)),
              (const char*)(W + (size_t)k * DMOD + bn) + (size_t)c16 * 16);
    }
    cpcommit();

    for (int s = 0; s < 8; s++) {
        cpwait0();
        __syncthreads();
        if (s < 7) {
            int ns = s + 1;
            uint32_t ab = sb + (uint32_t)((ns & 1) * 16384);
            uint32_t wb = sb + (uint32_t)(32768 + (ns & 1) * 16384);
#pragma unroll
            for (int i = 0; i < 4; i++) {
                int idx = i * 256 + tid;
                int row = idx >> 3;
                int c16 = idx & 7;
                cpa16(ab + (uint32_t)(row * 128 + ((c16 ^ (row & 7)) << 4)),
                      (const char*)(A + (size_t)(bm + row) * DMOD + (size_t)ns * 64) + (size_t)c16 * 16);
            }
#pragma unroll
            for (int i = 0; i < 4; i++) {
                int idx = i * 256 + tid;
                int k = idx >> 4;
                int c16 = idx & 15;
                cpa16(wb + (uint32_t)(k * 256 + ((c16 ^ (k & 7)) << 4)),
                      (const char*)(W + (size_t)(ns * 64 + k) * DMOD + bn) + (size_t)c16 * 16);
            }
            cpcommit();
        }
        uint32_t sa = sb + (uint32_t)((s & 1) * 16384);
        uint32_t sw = sb + (uint32_t)(32768 + (s & 1) * 16384);
#pragma unroll
        for (int ks = 0; ks < 4; ks++) {
            uint32_t am[4][4];
            int ck = ks * 2 + cP8;
#pragma unroll
            for (int mt = 0; mt < 4; mt++) {
                int rowA = wm * 64 + mt * 16 + rP;
                ldm4(am[mt][0], am[mt][1], am[mt][2], am[mt][3], sa + (uint32_t)(rowA * 128 + ((ck ^ (rowA & 7)) << 4)));
            }
#pragma unroll
            for (int nt2 = 0; nt2 < 2; nt2++) {
                uint32_t b0, b1, b2, b3;
                int rv = ks * 16 + rP;
                int cv = wn * 4 + nt2 * 2 + cP8;
                ldm4t(b0, b1, b2, b3, sw + (uint32_t)(rv * 256 + ((cv ^ (rv & 7)) << 4)));
#pragma unroll
                for (int mt = 0; mt < 4; mt++) {
                    mmab(acc[mt][2*nt2  ][0], acc[mt][2*nt2  ][1], acc[mt][2*nt2  ][2], acc[mt][2*nt2  ][3], am[mt][0], am[mt][1], am[mt][2], am[mt][3], b0, b1);
                    mmab(acc[mt][2*nt2+1][0], acc[mt][2*nt2+1][1], acc[mt][2*nt2+1][2], acc[mt][2*nt2+1][3], am[mt][0], am[mt][1], am[mt][2], am[mt][3], b2, b3);
                }
            }
        }
    }

#pragma unroll
    for (int mt = 0; mt < 4; mt++) {
        int row0 = bm + wm * 64 + mt * 16 + gid;
        int row1 = row0 + 8;
#pragma unroll
        for (int nt = 0; nt < 4; nt++) {
            int col = bn + wn * 32 + nt * 8 + tig * 2;
            float bx = bias[col];
            float by = bias[col + 1];
            *(__nv_bfloat162*)&out[(size_t)row0 * DMOD + col] = __floats2bfloat162_rn(acc[mt][nt][0] + bx, acc[mt][nt][1] + by);
            *(__nv_bfloat162*)&out[(size_t)row1 * DMOD + col] = __floats2bfloat162_rn(acc[mt][nt][2] + bx, acc[mt][nt][3] + by);
        }
    }
}

// ------------- bf16 output projection GEMM: out = A@W + bias + resid (fp32) -------------
__global__ __launch_bounds__(256)
void gemm_out(const __nv_bfloat16* __restrict__ A, const __nv_bfloat16* __restrict__ W,
              const float* __restrict__ bias, const float* __restrict__ resid,
              float* __restrict__ out)
{
    extern __shared__ char smg[];
    uint32_t sb = (uint32_t)__cvta_generic_to_shared(smg);

    const int tid  = threadIdx.x;
    const int wd   = tid >> 5;
    const int lane = tid & 31;
    const int r8   = lane & 7;
    const int jj   = lane >> 3;
    const int gid  = lane >> 2;
    const int tig  = lane & 3;
    const int wm   = wd >> 2;
    const int wn   = wd & 3;
    const int bm   = blockIdx.x * 128;
    const int bn   = blockIdx.y * 128;
    const int rP   = r8 + ((jj & 1) << 3);
    const int cP8  = jj >> 1;

    float acc[4][4][4];
#pragma unroll
    for (int mt = 0; mt < 4; mt++)
#pragma unroll
        for (int nt = 0; nt < 4; nt++)
#pragma unroll
            for (int q2 = 0; q2 < 4; q2++) { acc[mt][nt][q2] = 0.f; }

#pragma unroll
    for (int i = 0; i < 4; i++) {
        int idx = i * 256 + tid;
        int row = idx >> 3;
        int c16 = idx & 7;
        cpa16(sb + (uint32_t)(row * 128 + ((c16 ^ (row & 7)) << 4)),
              (const char*)(A + (size_t)(bm + row) * DMOD) + (size_t)c16 * 16);
    }
#pragma unroll
    for (int i = 0; i < 4; i++) {
        int idx = i * 256 + tid;
        int k = idx >> 4;
        int c16 = idx & 15;
        cpa16(sb + (uint32_t)(32768 + k * 256 + ((c16 ^ (k & 7)) << 4)),
              (const char*)(W + (size_t)k * DMOD + bn) + (size_t)c16 * 16);
    }
    cpcommit();

    for (int s = 0; s < 8; s++) {
        cpwait0();
        __syncthreads();
        if (s < 7) {
            int ns = s + 1;
            uint32_t ab = sb + (uint32_t)((ns & 1) * 16384);
            uint32_t wb = sb + (uint32_t)(32768 + (ns & 1) * 16384);
#pragma unroll
            for (int i = 0; i < 4; i++) {
                int idx = i * 256 + tid;
                int row = idx >> 3;
                int c16 = idx & 7;
                cpa16(ab + (uint32_t)(row * 128 + ((c16 ^ (row & 7)) << 4)),
                      (const char*)(A + (size_t)(bm + row) * DMOD + (size_t)ns * 64) + (size_t)c16 * 16);
            }
#pragma unroll
            for (int i = 0; i < 4; i++) {
                int idx = i * 256 + tid;
                int k = idx >> 4;
                int c16 = idx & 15;
                cpa16(wb + (uint32_t)(k * 256 + ((c16 ^ (k & 7)) << 4)),
                      (const char*)(W + (size_t)(ns * 64 + k) * DMOD + bn) + (size_t)c16 * 16);
            }
            cpcommit();
        }
        uint32_t sa = sb + (uint32_t)((s & 1) * 16384);
        uint32_t sw = sb + (uint32_t)(32768 + (s & 1) * 16384);
#pragma unroll
        for (int ks = 0; ks < 4; ks++) {
            uint32_t am[4][4];
            int ck = ks * 2 + cP8;
#pragma unroll
            for (int mt = 0; mt < 4; mt++) {
                int rowA = wm * 64 + mt * 16 + rP;
                ldm4(am[mt][0], am[mt][1], am[mt][2], am[mt][3], sa + (uint32_t)(rowA * 128 + ((ck ^ (rowA & 7)) << 4)));
            }
#pragma unroll
            for (int nt2 = 0; nt2 < 2; nt2++) {
                uint32_t b0, b1, b2, b3;
                int rv = ks * 16 + rP;
                int cv = wn * 4 + nt2 * 2 + cP8;
                ldm4t(b0, b1, b2, b3, sw + (uint32_t)(rv * 256 + ((cv ^ (rv & 7)) << 4)));
#pragma unroll
                for (int mt = 0; mt < 4; mt++) {
                    mmab(acc[mt][2*nt2  ][0], acc[mt][2*nt2  ][1], acc[mt][2*nt2  ][2], acc[mt][2*nt2  ][3], am[mt][0], am[mt][1], am[mt][2], am[mt][3], b0, b1);
                    mmab(acc[mt][2*nt2+1][0], acc[mt][2*nt2+1][1], acc[mt][2*nt2+1][2], acc[mt][2*nt2+1][3], am[mt][0], am[mt][1], am[mt][2], am[mt][3], b2, b3);
                }
            }
        }
    }

#pragma unroll
    for (int mt = 0; mt < 4; mt++) {
        int row0 = bm + wm * 64 + mt * 16 + gid;
        int row1 = row0 + 8;
#pragma unroll
        for (int nt = 0; nt < 4; nt++) {
            int col = bn + wn * 32 + nt * 8 + tig * 2;
            float bx = bias[col];
            float by = bias[col + 1];
            float2 ra = *(const float2*)&resid[(size_t)row0 * DMOD + col];
            float2 rb = *(const float2*)&resid[(size_t)row1 * DMOD + col];
            float2 v0 = make_float2(acc[mt][nt][0] + bx + ra.x, acc[mt][nt][1] + by + ra.y);
            float2 v1 = make_float2(acc[mt][nt][2] + bx + rb.x, acc[mt][nt][3] + by + rb.y);
            *(float2*)&out[(size_t)row0 * DMOD + col] = v0;
            *(float2*)&out[(size_t)row1 * DMOD + col] = v1;
        }
    }
}

__global__ void convf2b(const float* __restrict__ s, __nv_bfloat16* __restrict__ d, int n4)
{
    int i = blockIdx.x * blockDim.x + threadIdx.x;
    if (i < n4) {
        float4 v = ((const float4*)s)[i];
        ((__nv_bfloat162*)d)[2 * i]     = __floats2bfloat162_rn(v.x, v.y);
        ((__nv_bfloat162*)d)[2 * i + 1] = __floats2bfloat162_rn(v.z, v.w);
    }
}

// all 4 weight conversions in one launch
__global__ void convw4(const float* __restrict__ Wq, const float* __restrict__ Wk,
                       const float* __restrict__ Wv, const float* __restrict__ Wo)
{
    int i = blockIdx.x * blockDim.x + threadIdx.x;   // 0 .. 4*65536-1
    int w = i >> 16;
    int j = i & 65535;
    const float* s;
    __nv_bfloat16* d;
    if (w == 0)      { s = Wq; d = g_w0; }
    else if (w == 1) { s = Wk; d = g_w1; }
    else if (w == 2) { s = Wv; d = g_w2; }
    else             { s = Wo; d = g_w3; }
    float4 v = ((const float4*)s)[j];
    ((__nv_bfloat162*)d)[2 * j]     = __floats2bfloat162_rn(v.x, v.y);
    ((__nv_bfloat162*)d)[2 * j + 1] = __floats2bfloat162_rn(v.z, v.w);
}

__global__ void cls_kernel(float* __restrict__ out)
{
    int m = blockIdx.x * 256 + threadIdx.x;
    out[m] = g_cls[m] / g_Z0;
}

extern "C" void kernel_launch(void* const* d_in, const int* in_sizes, int n_in,
                              void* d_out, int out_size)
{
    const float* x  = (const float*)d_in[0];
    const float* Wq = (const float*)d_in[1];
    const float* bq = (const float*)d_in[2];
    const float* Wk = (const float*)d_in[3];
    const float* bk = (const float*)d_in[4];
    const float* Wv = (const float*)d_in[5];
    const float* bv = (const float*)d_in[6];
    const float* Wo = (const float*)d_in[7];
    const float* bo = (const float*)d_in[8];
    float* out = (float*)d_out;

    __nv_bfloat16 *xb = 0, *w0 = 0, *w1 = 0, *w2 = 0, *w3 = 0, *qb = 0, *kb = 0, *vb = 0, *ab = 0;
    cudaGetSymbolAddress((void**)&xb, g_xb);
    cudaGetSymbolAddress((void**)&w0, g_w0);
    cudaGetSymbolAddress((void**)&w1, g_w1);
    cudaGetSymbolAddress((void**)&w2, g_w2);
    cudaGetSymbolAddress((void**)&w3, g_w3);
    cudaGetSymbolAddress((void**)&qb, g_qb);
    cudaGetSymbolAddress((void**)&kb, g_kb);
    cudaGetSymbolAddress((void**)&vb, g_vb);
    cudaGetSymbolAddress((void**)&ab, g_ab);

    cudaFuncSetAttribute(attn2, cudaFuncAttributeMaxDynamicSharedMemorySize, SM_TOTAL);
    cudaFuncSetAttribute(gemm_qkv, cudaFuncAttributeMaxDynamicSharedMemorySize, 65536);
    cudaFuncSetAttribute(gemm_out, cudaFuncAttributeMaxDynamicSharedMemorySize, 65536);

    convf2b<<<4096, 256>>>(x, xb, NTOK * DMOD / 4);
    convw4<<<1024, 256>>>(Wq, Wk, Wv, Wo);

    dim3 gq(64, 4, 3);
    gemm_qkv<<<gq, 256, 65536>>>(xb, w0, w1, w2, bq, bk, bv, qb, kb, vb);

    attn2<<<256, 512, SM_TOTAL>>>();

    dim3 gg(64, 4);
    gemm_out<<<gg, 256, 65536>>>(ab, w3, bo, x, out);
    cls_kernel<<<32, 256>>>(out + (size_t)NTOK * DMOD);
}